// round 1
// baseline (speedup 1.0000x reference)
#include <cuda_runtime.h>
#include <cstdint>

#define NN 100000
#define NE 1600000
#define DD 128
#define NG 128

// ---------------- scratch (static device globals; no runtime allocation) ----
__device__ __align__(16) float g_agg[NN * DD];
__device__ __align__(16) float g_tmp[NN * DD];
__device__ __align__(16) float g_h[NN * DD];
__device__ int g_deg[NN];
__device__ int g_rowptr[NN + 1];
__device__ int g_cursor[NN];
__device__ int g_esorted[NE];
__device__ int g_idx64;   // 1 if edge_index/batch are int64, 0 if int32

// ---------------- index-width detection ------------------------------------
__global__ void detect_kernel(const void* ei_raw) {
    // edge src values are uniform in [0,100000). If stored as int64 (little
    // endian), every odd 32-bit word of the first entries is 0. If int32,
    // those words are independent edge values (P(all zero) ~ 1e-640).
    const unsigned* w = (const unsigned*)ei_raw;
    int is64 = 1;
    for (int i = 0; i < 128; i++) {
        if (w[2 * i + 1] != 0u) { is64 = 0; break; }
    }
    g_idx64 = is64;
}

__device__ __forceinline__ int load_idx(const void* p, long i) {
    if (g_idx64) return (int)((const long long*)p)[i];
    return ((const int*)p)[i];
}

// ---------------- CSR build -------------------------------------------------
__global__ void zero_deg_kernel() {
    int i = blockIdx.x * blockDim.x + threadIdx.x;
    if (i < NN) g_deg[i] = 0;
}

__global__ void hist_kernel(const void* __restrict__ ei) {
    int e = blockIdx.x * blockDim.x + threadIdx.x;
    if (e < NE) {
        int dst = load_idx(ei, (long)NE + e);
        atomicAdd(&g_deg[dst], 1);
    }
}

__global__ void scan_kernel() {
    __shared__ int ssum[1024];
    const int CH = 98;   // 1024*98 = 100352 >= NN
    int t = threadIdx.x;
    int base = t * CH;
    int s = 0;
    for (int i = 0; i < CH; i++) {
        int idx = base + i;
        if (idx < NN) s += g_deg[idx];
    }
    ssum[t] = s;
    __syncthreads();
    // inclusive Hillis-Steele scan over 1024 partials
    for (int off = 1; off < 1024; off <<= 1) {
        int v = (t >= off) ? ssum[t - off] : 0;
        __syncthreads();
        ssum[t] += v;
        __syncthreads();
    }
    int ex = (t == 0) ? 0 : ssum[t - 1];
    for (int i = 0; i < CH; i++) {
        int idx = base + i;
        if (idx < NN) {
            int d = g_deg[idx];
            g_rowptr[idx] = ex;
            g_cursor[idx] = ex;
            ex += d;
        }
    }
    if (t == 1023) g_rowptr[NN] = ssum[1023];
}

__global__ void fill_kernel(const void* __restrict__ ei) {
    int e = blockIdx.x * blockDim.x + threadIdx.x;
    if (e < NE) {
        int dst = load_idx(ei, (long)NE + e);
        int src = load_idx(ei, e);
        int pos = atomicAdd(&g_cursor[dst], 1);
        g_esorted[pos] = src;
    }
}

// ---------------- aggregation: out[i] = hin[i] + sum_{j in N(i)} hin[j] -----
__global__ void aggregate_kernel(const float* __restrict__ hin,
                                 float* __restrict__ hout) {
    int node = (blockIdx.x * blockDim.x + threadIdx.x) >> 5;
    int lane = threadIdx.x & 31;
    if (node >= NN) return;
    const float4* h4 = (const float4*)hin;
    float4 acc = h4[node * 32 + lane];
    int beg = g_rowptr[node];
    int end = g_rowptr[node + 1];
    for (int j = beg; j < end; j++) {
        int s = g_esorted[j];
        float4 v = __ldg(&h4[s * 32 + lane]);
        acc.x += v.x; acc.y += v.y; acc.z += v.z; acc.w += v.w;
    }
    ((float4*)hout)[node * 32 + lane] = acc;
}

// ---------------- fp32 GEMM via packed f32x2 FFMA ---------------------------
__device__ __forceinline__ unsigned long long pack2(float a) {
    unsigned long long r;
    unsigned ai = __float_as_uint(a);
    asm("mov.b64 %0, {%1, %1};" : "=l"(r) : "r"(ai));
    return r;
}
__device__ __forceinline__ void fma2(unsigned long long& acc,
                                     unsigned long long a,
                                     unsigned long long b) {
    asm("fma.rn.f32x2 %0, %1, %2, %0;" : "+l"(acc) : "l"(a), "l"(b));
}
__device__ __forceinline__ float2 unpack2(unsigned long long v) {
    float2 f;
    asm("mov.b64 {%0, %1}, %2;" : "=f"(f.x), "=f"(f.y) : "l"(v));
    return f;
}

// C[100000,128] = A[100000,128] @ W[128,128] + bias (+ optional relu)
// 256 threads, 64 rows per block; thread = 4 rows x 8 cols.
__global__ void __launch_bounds__(256) gemm_kernel(
        const float* __restrict__ A, const float* __restrict__ W,
        const float* __restrict__ bias, float* __restrict__ C,
        int relu_flag) {
    extern __shared__ float sW[];   // 128x128 fp32 = 64KB
    int tid = threadIdx.x;
    {
        const float4* W4 = (const float4*)W;
        float4* sW4 = (float4*)sW;
        #pragma unroll
        for (int i = 0; i < 16; i++) sW4[tid + 256 * i] = W4[tid + 256 * i];
    }
    __syncthreads();

    int tx = tid & 15;    // column group: cols tx*8 .. tx*8+7
    int ty = tid >> 4;    // row group: 4 rows
    int rbase = blockIdx.x * 64 + ty * 4;

    const float4* A4 = (const float4*)A;
    int rofs[4];
    #pragma unroll
    for (int rr = 0; rr < 4; rr++) {
        int r = rbase + rr;
        rofs[rr] = (r < NN ? r : NN - 1) * 32;
    }

    unsigned long long acc[4][4];
    #pragma unroll
    for (int rr = 0; rr < 4; rr++)
        #pragma unroll
        for (int c = 0; c < 4; c++) acc[rr][c] = 0ULL;

    const ulonglong2* sW2 = (const ulonglong2*)sW;   // 32 u64x2 per k-row

    for (int k4 = 0; k4 < 32; k4++) {
        float4 a[4];
        #pragma unroll
        for (int rr = 0; rr < 4; rr++) a[rr] = __ldg(&A4[rofs[rr] + k4]);
        #pragma unroll
        for (int j = 0; j < 4; j++) {
            int k = k4 * 4 + j;
            ulonglong2 wA = sW2[k * 32 + tx * 2];
            ulonglong2 wB = sW2[k * 32 + tx * 2 + 1];
            #pragma unroll
            for (int rr = 0; rr < 4; rr++) {
                float av = (j == 0) ? a[rr].x : (j == 1) ? a[rr].y
                         : (j == 2) ? a[rr].z : a[rr].w;
                unsigned long long aa = pack2(av);
                fma2(acc[rr][0], aa, wA.x);
                fma2(acc[rr][1], aa, wA.y);
                fma2(acc[rr][2], aa, wB.x);
                fma2(acc[rr][3], aa, wB.y);
            }
        }
    }

    float bv[8];
    #pragma unroll
    for (int c = 0; c < 8; c++) bv[c] = bias[tx * 8 + c];

    #pragma unroll
    for (int rr = 0; rr < 4; rr++) {
        int r = rbase + rr;
        if (r < NN) {
            float o[8];
            #pragma unroll
            for (int c = 0; c < 4; c++) {
                float2 f = unpack2(acc[rr][c]);
                o[c * 2]     = f.x + bv[c * 2];
                o[c * 2 + 1] = f.y + bv[c * 2 + 1];
            }
            if (relu_flag) {
                #pragma unroll
                for (int c = 0; c < 8; c++) o[c] = fmaxf(o[c], 0.f);
            }
            float4* Cr = (float4*)&C[r * DD + tx * 8];
            Cr[0] = make_float4(o[0], o[1], o[2], o[3]);
            Cr[1] = make_float4(o[4], o[5], o[6], o[7]);
        }
    }
}

// ---------------- mean pool over sorted batch --------------------------------
__device__ __forceinline__ int lbound_batch(const void* b, int val) {
    int lo = 0, hi = NN;
    if (g_idx64) {
        const long long* p = (const long long*)b;
        long long v = val;
        while (lo < hi) { int mid = (lo + hi) >> 1; if (p[mid] < v) lo = mid + 1; else hi = mid; }
    } else {
        const int* p = (const int*)b;
        while (lo < hi) { int mid = (lo + hi) >> 1; if (p[mid] < val) lo = mid + 1; else hi = mid; }
    }
    return lo;
}

__global__ void pool_kernel(const float* __restrict__ h,
                            const void* __restrict__ batch,
                            float* __restrict__ out) {
    int g = blockIdx.x;
    int d = threadIdx.x & 127;
    int sub = threadIdx.x >> 7;   // 0..3
    int start = lbound_batch(batch, g);
    int end   = lbound_batch(batch, g + 1);
    float acc = 0.f;
    for (int n = start + sub; n < end; n += 4)
        acc += h[n * DD + d];
    __shared__ float red[512];
    red[threadIdx.x] = acc;
    __syncthreads();
    if (sub == 0) {
        float s = red[d] + red[d + 128] + red[d + 256] + red[d + 384];
        int cnt = end - start;
        out[g * DD + d] = s / (float)(cnt > 0 ? cnt : 1);
    }
}

// ---------------- launch ------------------------------------------------------
extern "C" void kernel_launch(void* const* d_in, const int* in_sizes, int n_in,
                              void* d_out, int out_size) {
    const float* x = (const float*)d_in[0];
    const void* ei = d_in[1];
    const void* batch = d_in[2];
    const float *W1[3], *b1[3], *W2[3], *b2[3];
    for (int l = 0; l < 3; l++) {
        W1[l] = (const float*)d_in[3 + 4 * l];
        b1[l] = (const float*)d_in[4 + 4 * l];
        W2[l] = (const float*)d_in[5 + 4 * l];
        b2[l] = (const float*)d_in[6 + 4 * l];
    }
    float* out = (float*)d_out;

    cudaFuncSetAttribute(gemm_kernel,
                         cudaFuncAttributeMaxDynamicSharedMemorySize, 65536);

    float *agg, *tmp, *h;
    cudaGetSymbolAddress((void**)&agg, g_agg);
    cudaGetSymbolAddress((void**)&tmp, g_tmp);
    cudaGetSymbolAddress((void**)&h, g_h);

    detect_kernel<<<1, 1>>>(ei);
    zero_deg_kernel<<<(NN + 255) / 256, 256>>>();
    hist_kernel<<<(NE + 255) / 256, 256>>>(ei);
    scan_kernel<<<1, 1024>>>();
    fill_kernel<<<(NE + 255) / 256, 256>>>(ei);

    const int gemm_blocks = (NN + 63) / 64;
    const int agg_blocks = (NN * 32 + 255) / 256;

    const float* hin = x;
    for (int l = 0; l < 3; l++) {
        aggregate_kernel<<<agg_blocks, 256>>>(hin, agg);
        gemm_kernel<<<gemm_blocks, 256, 65536>>>(agg, W1[l], b1[l], tmp, 1);
        gemm_kernel<<<gemm_blocks, 256, 65536>>>(tmp, W2[l], b2[l], h, (l < 2) ? 1 : 0);
        hin = h;
    }
    pool_kernel<<<NG, 512>>>(h, batch, out);
}

// round 2
// speedup vs baseline: 1.0516x; 1.0516x over previous
#include <cuda_runtime.h>
#include <cstdint>

#define NN 100000
#define NE 1600000
#define DD 128
#define NG 128

// ---------------- scratch (static device globals; no runtime allocation) ----
__device__ __align__(16) float g_tmp[NN * DD];
__device__ __align__(16) float g_h[NN * DD];
__device__ int g_deg[NN];
__device__ int g_rowptr[NN + 1];
__device__ int g_cursor[NN];
__device__ int g_esorted[NE];
__device__ int g_part[256];
__device__ int g_partscan[256];
__device__ int g_idx64;   // 1 if edge_index/batch are int64, 0 if int32

#define SCAN_B 512
#define SCAN_NB ((NN + SCAN_B - 1) / SCAN_B)   // 196

// ---------------- index-width detection ------------------------------------
__global__ void detect_kernel(const void* ei_raw) {
    // edge values are uniform in [0,100000). If int64 (little endian), every
    // odd 32-bit word of the first entries is 0 (P(false positive) ~ 1e-640).
    const unsigned* w = (const unsigned*)ei_raw;
    int is64 = 1;
    for (int i = 0; i < 128; i++) {
        if (w[2 * i + 1] != 0u) { is64 = 0; break; }
    }
    g_idx64 = is64;
}

__device__ __forceinline__ int load_idx(const void* p, long i) {
    if (g_idx64) return (int)((const long long*)p)[i];
    return ((const int*)p)[i];
}

// ---------------- CSR build -------------------------------------------------
__global__ void zero_deg_kernel() {
    int i = blockIdx.x * blockDim.x + threadIdx.x;
    if (i < NN) g_deg[i] = 0;
}

__global__ void hist_kernel(const void* __restrict__ ei) {
    int e = blockIdx.x * blockDim.x + threadIdx.x;
    if (e < NE) {
        int dst = load_idx(ei, (long)NE + e);
        atomicAdd(&g_deg[dst], 1);
    }
}

// scan stage 1: per-block sums of 512 degrees
__global__ void reduce_kernel() {
    int idx = blockIdx.x * SCAN_B + threadIdx.x;
    int v = (idx < NN) ? g_deg[idx] : 0;
    #pragma unroll
    for (int o = 16; o > 0; o >>= 1) v += __shfl_down_sync(~0u, v, o);
    __shared__ int sh[16];
    int lane = threadIdx.x & 31, wid = threadIdx.x >> 5;
    if (lane == 0) sh[wid] = v;
    __syncthreads();
    if (threadIdx.x < 16) {
        int s = sh[threadIdx.x];
        #pragma unroll
        for (int o = 8; o > 0; o >>= 1) s += __shfl_down_sync(0xffffu, s, o, 16);
        if (threadIdx.x == 0) g_part[blockIdx.x] = s;
    }
}

// scan stage 2: exclusive scan of 196 partials (1 block)
__global__ void partscan_kernel() {
    __shared__ int sh[256];
    int t = threadIdx.x;
    int v = (t < SCAN_NB) ? g_part[t] : 0;
    sh[t] = v;
    __syncthreads();
    for (int off = 1; off < 256; off <<= 1) {
        int u = (t >= off) ? sh[t - off] : 0;
        __syncthreads();
        sh[t] += u;
        __syncthreads();
    }
    g_partscan[t] = sh[t] - v;                 // exclusive
    if (t == SCAN_NB - 1) g_rowptr[NN] = sh[t]; // total = NE
}

// scan stage 3: block-local exclusive scan + partial offset
__global__ void localscan_kernel() {
    int t = threadIdx.x;
    int idx = blockIdx.x * SCAN_B + t;
    int v = (idx < NN) ? g_deg[idx] : 0;
    int lane = t & 31, wid = t >> 5;
    int x = v;
    #pragma unroll
    for (int o = 1; o < 32; o <<= 1) {
        int u = __shfl_up_sync(~0u, x, o);
        if (lane >= o) x += u;
    }
    __shared__ int ws[16];
    __shared__ int wo[16];
    if (lane == 31) ws[wid] = x;
    __syncthreads();
    if (t < 16) {
        int y = ws[t];
        int z = y;
        #pragma unroll
        for (int o = 1; o < 16; o <<= 1) {
            int u = __shfl_up_sync(0xffffu, z, o, 16);
            if (t >= o) z += u;
        }
        wo[t] = z - y;   // exclusive warp offset
    }
    __syncthreads();
    int excl = x - v + wo[wid] + g_partscan[blockIdx.x];
    if (idx < NN) { g_rowptr[idx] = excl; g_cursor[idx] = excl; }
}

__global__ void fill_kernel(const void* __restrict__ ei) {
    int e = blockIdx.x * blockDim.x + threadIdx.x;
    if (e < NE) {
        int dst = load_idx(ei, (long)NE + e);
        int src = load_idx(ei, e);
        int pos = atomicAdd(&g_cursor[dst], 1);
        g_esorted[pos] = src;
    }
}

// ---------------- packed f32x2 FMA helpers ----------------------------------
__device__ __forceinline__ unsigned long long pack2(float a) {
    unsigned long long r;
    unsigned ai = __float_as_uint(a);
    asm("mov.b64 %0, {%1, %1};" : "=l"(r) : "r"(ai));
    return r;
}
__device__ __forceinline__ void fma2(unsigned long long& acc,
                                     unsigned long long a,
                                     unsigned long long b) {
    asm("fma.rn.f32x2 %0, %1, %2, %0;" : "+l"(acc) : "l"(a), "l"(b));
}
__device__ __forceinline__ float2 unpack2(unsigned long long v) {
    float2 f;
    asm("mov.b64 {%0, %1}, %2;" : "=f"(f.x), "=f"(f.y) : "l"(v));
    return f;
}
__device__ __forceinline__ float selj(const float4& v, int j) {
    return j == 0 ? v.x : j == 1 ? v.y : j == 2 ? v.z : v.w;
}

// 128x128 @ 128x128 tile GEMM from smem A and smem W; thread = 4 rows x 8 cols.
__device__ __forceinline__ void tile_gemm(const float* __restrict__ sA,
                                          const float* __restrict__ sW,
                                          int tx, int rl, float o[4][8]) {
    unsigned long long acc[4][4];
    #pragma unroll
    for (int a = 0; a < 4; a++)
        #pragma unroll
        for (int b = 0; b < 4; b++) acc[a][b] = 0ULL;

    const ulonglong2* Wp = (const ulonglong2*)sW;   // 32 u64x2 per k-row
    #pragma unroll 4
    for (int k4 = 0; k4 < 32; k4++) {
        float4 a0 = ((const float4*)(sA + (rl + 0) * DD))[k4];
        float4 a1 = ((const float4*)(sA + (rl + 1) * DD))[k4];
        float4 a2 = ((const float4*)(sA + (rl + 2) * DD))[k4];
        float4 a3 = ((const float4*)(sA + (rl + 3) * DD))[k4];
        #pragma unroll
        for (int j = 0; j < 4; j++) {
            int k = k4 * 4 + j;
            ulonglong2 wA = Wp[k * 32 + tx * 2];
            ulonglong2 wB = Wp[k * 32 + tx * 2 + 1];
            unsigned long long p0 = pack2(selj(a0, j));
            unsigned long long p1 = pack2(selj(a1, j));
            unsigned long long p2 = pack2(selj(a2, j));
            unsigned long long p3 = pack2(selj(a3, j));
            fma2(acc[0][0], p0, wA.x); fma2(acc[0][1], p0, wA.y);
            fma2(acc[0][2], p0, wB.x); fma2(acc[0][3], p0, wB.y);
            fma2(acc[1][0], p1, wA.x); fma2(acc[1][1], p1, wA.y);
            fma2(acc[1][2], p1, wB.x); fma2(acc[1][3], p1, wB.y);
            fma2(acc[2][0], p2, wA.x); fma2(acc[2][1], p2, wA.y);
            fma2(acc[2][2], p2, wB.x); fma2(acc[2][3], p2, wB.y);
            fma2(acc[3][0], p3, wA.x); fma2(acc[3][1], p3, wA.y);
            fma2(acc[3][2], p3, wB.x); fma2(acc[3][3], p3, wB.y);
        }
    }
    #pragma unroll
    for (int rr = 0; rr < 4; rr++)
        #pragma unroll
        for (int c = 0; c < 4; c++) {
            float2 f = unpack2(acc[rr][c]);
            o[rr][c * 2]     = f.x;
            o[rr][c * 2 + 1] = f.y;
        }
}

// ---------------- fused layer: agg -> relu(A@W1+b1) -> @W2+b2 (+relu) -------
// 512 threads, 128-row tile. smem: W1(64K) | W2(64K) | A/T(64K) = 192KB.
__global__ void __launch_bounds__(512, 1) layer_kernel(
        const float* __restrict__ hin,
        const float* __restrict__ W1, const float* __restrict__ b1,
        const float* __restrict__ W2, const float* __restrict__ b2,
        float* __restrict__ hout, int relu2) {
    extern __shared__ float smem[];
    float* sW1 = smem;
    float* sW2 = smem + 16384;
    float* sA  = smem + 32768;
    int tid = threadIdx.x;

    // stage weights (no sync yet; overlapped with aggregation loads)
    {
        const float4* w14 = (const float4*)W1;
        const float4* w24 = (const float4*)W2;
        float4* s14 = (float4*)sW1;
        float4* s24 = (float4*)sW2;
        #pragma unroll
        for (int i = 0; i < 8; i++) {
            s14[tid + 512 * i] = w14[tid + 512 * i];
            s24[tid + 512 * i] = w24[tid + 512 * i];
        }
    }

    // aggregation: warp w -> rows w*8..w*8+7 of the 128-row tile
    {
        int lane = tid & 31, wid = tid >> 5;
        const float4* h4 = (const float4*)hin;
        #pragma unroll 2
        for (int rr = 0; rr < 8; rr++) {
            int row = wid * 8 + rr;
            int node = blockIdx.x * 128 + row;
            if (node >= NN) node = NN - 1;   // stores of OOB rows are guarded later
            float4 acc = __ldg(&h4[node * 32 + lane]);
            int beg = g_rowptr[node];
            int end = g_rowptr[node + 1];
            int j = beg;
            for (; j + 4 <= end; j += 4) {
                int s0 = g_esorted[j];
                int s1 = g_esorted[j + 1];
                int s2 = g_esorted[j + 2];
                int s3 = g_esorted[j + 3];
                float4 v0 = __ldg(&h4[s0 * 32 + lane]);
                float4 v1 = __ldg(&h4[s1 * 32 + lane]);
                float4 v2 = __ldg(&h4[s2 * 32 + lane]);
                float4 v3 = __ldg(&h4[s3 * 32 + lane]);
                acc.x += (v0.x + v1.x) + (v2.x + v3.x);
                acc.y += (v0.y + v1.y) + (v2.y + v3.y);
                acc.z += (v0.z + v1.z) + (v2.z + v3.z);
                acc.w += (v0.w + v1.w) + (v2.w + v3.w);
            }
            for (; j < end; j++) {
                int s = g_esorted[j];
                float4 v = __ldg(&h4[s * 32 + lane]);
                acc.x += v.x; acc.y += v.y; acc.z += v.z; acc.w += v.w;
            }
            ((float4*)(sA + row * DD))[lane] = acc;
        }
    }
    __syncthreads();

    int tx = tid & 15;     // col group: cols tx*8 .. tx*8+7
    int ty = tid >> 4;     // 0..31
    int rl = ty * 4;       // local row base

    float o[4][8];
    tile_gemm(sA, sW1, tx, rl, o);

    // bias1 + relu
    #pragma unroll
    for (int c = 0; c < 8; c++) {
        float bv = __ldg(&b1[tx * 8 + c]);
        #pragma unroll
        for (int rr = 0; rr < 4; rr++)
            o[rr][c] = fmaxf(o[rr][c] + bv, 0.f);
    }

    __syncthreads();   // all reads of sA done
    #pragma unroll
    for (int rr = 0; rr < 4; rr++) {
        float4* Tp = (float4*)(sA + (rl + rr) * DD + tx * 8);
        Tp[0] = make_float4(o[rr][0], o[rr][1], o[rr][2], o[rr][3]);
        Tp[1] = make_float4(o[rr][4], o[rr][5], o[rr][6], o[rr][7]);
    }
    __syncthreads();

    tile_gemm(sA, sW2, tx, rl, o);

    #pragma unroll
    for (int c = 0; c < 8; c++) {
        float bv = __ldg(&b2[tx * 8 + c]);
        #pragma unroll
        for (int rr = 0; rr < 4; rr++) {
            float v = o[rr][c] + bv;
            o[rr][c] = relu2 ? fmaxf(v, 0.f) : v;
        }
    }

    #pragma unroll
    for (int rr = 0; rr < 4; rr++) {
        int node = blockIdx.x * 128 + rl + rr;
        if (node < NN) {
            float4* Cp = (float4*)&hout[node * DD + tx * 8];
            Cp[0] = make_float4(o[rr][0], o[rr][1], o[rr][2], o[rr][3]);
            Cp[1] = make_float4(o[rr][4], o[rr][5], o[rr][6], o[rr][7]);
        }
    }
}

// ---------------- mean pool over sorted batch --------------------------------
__device__ __forceinline__ int lbound_batch(const void* b, int val) {
    int lo = 0, hi = NN;
    if (g_idx64) {
        const long long* p = (const long long*)b;
        long long v = val;
        while (lo < hi) { int mid = (lo + hi) >> 1; if (p[mid] < v) lo = mid + 1; else hi = mid; }
    } else {
        const int* p = (const int*)b;
        while (lo < hi) { int mid = (lo + hi) >> 1; if (p[mid] < val) lo = mid + 1; else hi = mid; }
    }
    return lo;
}

__global__ void pool_kernel(const float* __restrict__ h,
                            const void* __restrict__ batch,
                            float* __restrict__ out) {
    int g = blockIdx.x;
    int d = threadIdx.x & 127;
    int sub = threadIdx.x >> 7;   // 0..3
    int start = lbound_batch(batch, g);
    int end   = lbound_batch(batch, g + 1);
    float acc = 0.f;
    for (int n = start + sub; n < end; n += 4)
        acc += h[n * DD + d];
    __shared__ float red[512];
    red[threadIdx.x] = acc;
    __syncthreads();
    if (sub == 0) {
        float s = (red[d] + red[d + 128]) + (red[d + 256] + red[d + 384]);
        int cnt = end - start;
        out[g * DD + d] = s / (float)(cnt > 0 ? cnt : 1);
    }
}

// ---------------- launch ------------------------------------------------------
extern "C" void kernel_launch(void* const* d_in, const int* in_sizes, int n_in,
                              void* d_out, int out_size) {
    const float* x = (const float*)d_in[0];
    const void* ei = d_in[1];
    const void* batch = d_in[2];
    const float *W1[3], *b1[3], *W2[3], *b2[3];
    for (int l = 0; l < 3; l++) {
        W1[l] = (const float*)d_in[3 + 4 * l];
        b1[l] = (const float*)d_in[4 + 4 * l];
        W2[l] = (const float*)d_in[5 + 4 * l];
        b2[l] = (const float*)d_in[6 + 4 * l];
    }
    float* out = (float*)d_out;

    cudaFuncSetAttribute(layer_kernel,
                         cudaFuncAttributeMaxDynamicSharedMemorySize, 196608);

    float *tmp, *h;
    cudaGetSymbolAddress((void**)&tmp, g_tmp);
    cudaGetSymbolAddress((void**)&h, g_h);

    detect_kernel<<<1, 1>>>(ei);
    zero_deg_kernel<<<(NN + 255) / 256, 256>>>();
    hist_kernel<<<(NE + 255) / 256, 256>>>(ei);
    reduce_kernel<<<SCAN_NB, SCAN_B>>>();
    partscan_kernel<<<1, 256>>>();
    localscan_kernel<<<SCAN_NB, SCAN_B>>>();
    fill_kernel<<<(NE + 255) / 256, 256>>>(ei);

    const int layer_blocks = (NN + 127) / 128;   // 782
    layer_kernel<<<layer_blocks, 512, 196608>>>(x,   W1[0], b1[0], W2[0], b2[0], h,   1);
    layer_kernel<<<layer_blocks, 512, 196608>>>(h,   W1[1], b1[1], W2[1], b2[1], tmp, 1);
    layer_kernel<<<layer_blocks, 512, 196608>>>(tmp, W1[2], b1[2], W2[2], b2[2], h,   0);

    pool_kernel<<<NG, 512>>>(h, batch, out);
}

// round 4
// speedup vs baseline: 2.0293x; 1.9297x over previous
#include <cuda_runtime.h>
#include <cuda_bf16.h>
#include <cstdint>

#define NN 100000
#define NE 1600000
#define DD 128
#define NG 128

// ---------------- scratch (static device globals; no runtime allocation) ----
__device__ __align__(16) float g_tmp[NN * DD];
__device__ __align__(16) float g_h[NN * DD];
__device__ int g_deg[NN];
__device__ int g_rowptr[NN + 1];
__device__ int g_cursor[NN];
__device__ int g_esorted[NE];
__device__ int g_part[256];
__device__ int g_partscan[256];
__device__ int g_idx64;
// pre-transposed, pre-swizzled bf16 hi/lo weights: [6] = {W1_0,W2_0,W1_1,W2_1,W1_2,W2_2}
// element (n,k) at n*128 + (((k>>3) ^ (n&7))<<3) + (k&7)
__device__ __align__(16) __nv_bfloat16 g_whi[6][16384];
__device__ __align__(16) __nv_bfloat16 g_wlo[6][16384];

#define SCAN_B 512
#define SCAN_NB ((NN + SCAN_B - 1) / SCAN_B)   // 196

// ---------------- index-width detection ------------------------------------
__global__ void detect_kernel(const void* ei_raw) {
    const unsigned* w = (const unsigned*)ei_raw;
    int is64 = 1;
    for (int i = 0; i < 128; i++) {
        if (w[2 * i + 1] != 0u) { is64 = 0; break; }
    }
    g_idx64 = is64;
}

__device__ __forceinline__ int load_idx(const void* p, long i) {
    if (g_idx64) return (int)((const long long*)p)[i];
    return ((const int*)p)[i];
}

// ---------------- CSR build -------------------------------------------------
__global__ void zero_deg_kernel() {
    int i = blockIdx.x * blockDim.x + threadIdx.x;
    if (i < NN) g_deg[i] = 0;
}

__global__ void hist_kernel(const void* __restrict__ ei) {
    int e = blockIdx.x * blockDim.x + threadIdx.x;
    if (e < NE) {
        int dst = load_idx(ei, (long)NE + e);
        atomicAdd(&g_deg[dst], 1);
    }
}

__global__ void reduce_kernel() {
    int idx = blockIdx.x * SCAN_B + threadIdx.x;
    int v = (idx < NN) ? g_deg[idx] : 0;
    #pragma unroll
    for (int o = 16; o > 0; o >>= 1) v += __shfl_down_sync(~0u, v, o);
    __shared__ int sh[16];
    int lane = threadIdx.x & 31, wid = threadIdx.x >> 5;
    if (lane == 0) sh[wid] = v;
    __syncthreads();
    if (threadIdx.x < 16) {
        int s = sh[threadIdx.x];
        #pragma unroll
        for (int o = 8; o > 0; o >>= 1) s += __shfl_down_sync(0xffffu, s, o, 16);
        if (threadIdx.x == 0) g_part[blockIdx.x] = s;
    }
}

__global__ void partscan_kernel() {
    __shared__ int sh[256];
    int t = threadIdx.x;
    int v = (t < SCAN_NB) ? g_part[t] : 0;
    sh[t] = v;
    __syncthreads();
    for (int off = 1; off < 256; off <<= 1) {
        int u = (t >= off) ? sh[t - off] : 0;
        __syncthreads();
        sh[t] += u;
        __syncthreads();
    }
    g_partscan[t] = sh[t] - v;
    if (t == SCAN_NB - 1) g_rowptr[NN] = sh[t];
}

__global__ void localscan_kernel() {
    int t = threadIdx.x;
    int idx = blockIdx.x * SCAN_B + t;
    int v = (idx < NN) ? g_deg[idx] : 0;
    int lane = t & 31, wid = t >> 5;
    int x = v;
    #pragma unroll
    for (int o = 1; o < 32; o <<= 1) {
        int u = __shfl_up_sync(~0u, x, o);
        if (lane >= o) x += u;
    }
    __shared__ int ws[16];
    __shared__ int wo[16];
    if (lane == 31) ws[wid] = x;
    __syncthreads();
    if (t < 16) {
        int y = ws[t];
        int z = y;
        #pragma unroll
        for (int o = 1; o < 16; o <<= 1) {
            int u = __shfl_up_sync(0xffffu, z, o, 16);
            if (t >= o) z += u;
        }
        wo[t] = z - y;
    }
    __syncthreads();
    int excl = x - v + wo[wid] + g_partscan[blockIdx.x];
    if (idx < NN) { g_rowptr[idx] = excl; g_cursor[idx] = excl; }
}

__global__ void fill_kernel(const void* __restrict__ ei) {
    int e = blockIdx.x * blockDim.x + threadIdx.x;
    if (e < NE) {
        int dst = load_idx(ei, (long)NE + e);
        int src = load_idx(ei, e);
        int pos = atomicAdd(&g_cursor[dst], 1);
        g_esorted[pos] = src;
    }
}

// ---------------- weight prep: W[k][n] fp32 -> Wt[n][k] bf16 hi/lo ----------
__device__ __forceinline__ uint32_t w_off(int n, int k) {
    return (uint32_t)(n * 128 + (((k >> 3) ^ (n & 7)) << 3) + (k & 7));
}

__global__ void prep_kernel(const float* w0, const float* w1, const float* w2,
                            const float* w3, const float* w4, const float* w5) {
    const float* src[6] = {w0, w1, w2, w3, w4, w5};
    int b = blockIdx.x;
    const float* W = src[b];
    for (int i = threadIdx.x; i < 16384; i += blockDim.x) {
        int k = i >> 7, n = i & 127;
        float v = W[i];
        __nv_bfloat16 hi = __float2bfloat16(v);
        __nv_bfloat16 lo = __float2bfloat16(v - __bfloat162float(hi));
        uint32_t idx = w_off(n, k);
        g_whi[b][idx] = hi;
        g_wlo[b][idx] = lo;
    }
}

// ---------------- warp-MMA helpers ------------------------------------------
__device__ __forceinline__ uint32_t smem_u32(const void* p) {
    uint32_t a;
    asm("{ .reg .u64 t; cvta.to.shared.u64 t, %1; cvt.u32.u64 %0, t; }"
        : "=r"(a) : "l"(p));
    return a;
}
__device__ __forceinline__ void ldsm4(unsigned r[4], uint32_t addr) {
    asm volatile("ldmatrix.sync.aligned.m8n8.x4.shared.b16 {%0,%1,%2,%3}, [%4];"
                 : "=r"(r[0]), "=r"(r[1]), "=r"(r[2]), "=r"(r[3]) : "r"(addr));
}
__device__ __forceinline__ void mma16816(float c[4], const unsigned a[4],
                                         const unsigned b[2]) {
    asm volatile(
        "mma.sync.aligned.m16n8k16.row.col.f32.bf16.bf16.f32 "
        "{%0,%1,%2,%3}, {%4,%5,%6,%7}, {%8,%9}, {%0,%1,%2,%3};"
        : "+f"(c[0]), "+f"(c[1]), "+f"(c[2]), "+f"(c[3])
        : "r"(a[0]), "r"(a[1]), "r"(a[2]), "r"(a[3]), "r"(b[0]), "r"(b[1]));
}

// one 64x128 @ 128x128 stage; warp = 16 rows x 64 cols (8 n-tiles), 3-product split
__device__ __forceinline__ void mma_stage(uint32_t aHi, uint32_t aLo,
                                          uint32_t wHi, uint32_t wLo,
                                          int mbase, int nhalf, int lane,
                                          float c[8][4]) {
    #pragma unroll
    for (int i = 0; i < 8; i++)
        #pragma unroll
        for (int q = 0; q < 4; q++) c[i][q] = 0.f;

    int m = lane >> 3, r = lane & 7;
    int arow = mbase + (m & 1) * 8 + r;
    int aAdd = m >> 1;                 // chunk offset 0/1
    uint32_t aOffH = aHi + arow * 256;
    uint32_t aOffL = aLo + arow * 256;
    int brow0 = nhalf * 64 + (m >> 1) * 8 + r;
    int bAdd = m & 1;

    #pragma unroll
    for (int k = 0; k < 8; k++) {
        unsigned ah[4], al[4];
        uint32_t ac = (uint32_t)(((k * 2 + aAdd) ^ r) << 4);
        ldsm4(ah, aOffH + ac);
        ldsm4(al, aOffL + ac);
        uint32_t bc = (uint32_t)(((k * 2 + bAdd) ^ r) << 4);
        #pragma unroll
        for (int j = 0; j < 4; j++) {
            uint32_t brow = (uint32_t)(brow0 + j * 16) * 256;
            unsigned bh[4], bl[4];
            ldsm4(bh, wHi + brow + bc);
            ldsm4(bl, wLo + brow + bc);
            mma16816(c[2 * j],     ah, bh);
            mma16816(c[2 * j],     al, bh);
            mma16816(c[2 * j],     ah, bl);
            mma16816(c[2 * j + 1], ah, bh + 2);
            mma16816(c[2 * j + 1], al, bh + 2);
            mma16816(c[2 * j + 1], ah, bl + 2);
        }
    }
}

__device__ __forceinline__ void store_hilo(char* pH, char* pL, int row, int col,
                                           float f0, float f1) {
    __nv_bfloat16 h0 = __float2bfloat16(f0), h1 = __float2bfloat16(f1);
    __nv_bfloat16 l0 = __float2bfloat16(f0 - __bfloat162float(h0));
    __nv_bfloat16 l1 = __float2bfloat16(f1 - __bfloat162float(h1));
    uint32_t off = (uint32_t)(row * 256 + (((col >> 3) ^ (row & 7)) << 4)
                              + (col & 7) * 2);
    *(__nv_bfloat162*)(pH + off) = __halves2bfloat162(h0, h1);
    *(__nv_bfloat162*)(pL + off) = __halves2bfloat162(l0, l1);
}

// ---------------- fused layer: gather -> MMA1 -> relu -> MMA2 ---------------
// 256 threads, 64-row tile, 96KB smem -> 2 CTAs/SM (gather/MMA overlap).
__global__ void __launch_bounds__(256, 2) layer_kernel(
        const float* __restrict__ hin,
        const float* __restrict__ b1, const float* __restrict__ b2,
        float* __restrict__ hout, int widx, int relu2) {
    extern __shared__ char smem[];
    char* pAhi = smem;             // 64 x 256B = 16KB
    char* pAlo = smem + 16384;     // 16KB
    char* pWhi = smem + 32768;     // 128 x 256B = 32KB
    char* pWlo = smem + 65536;     // 32KB

    int tid = threadIdx.x;
    int lane = tid & 31, wid = tid >> 5;
    int nodeBase = blockIdx.x * 64;

    // ---- stage W1 (pre-swizzled; straight copy) ----
    {
        const float4* sh = (const float4*)g_whi[widx];
        const float4* sl = (const float4*)g_wlo[widx];
        float4* dh = (float4*)pWhi;
        float4* dl = (float4*)pWlo;
        #pragma unroll
        for (int i = 0; i < 8; i++) {
            int j = tid + 256 * i;
            dh[j] = sh[j];
            dl[j] = sl[j];
        }
    }

    // ---- gather: warp w -> rows w*8 .. w*8+7; write bf16 hi/lo into A tiles ----
    {
        const float4* h4 = (const float4*)hin;
        #pragma unroll 2
        for (int rr = 0; rr < 8; rr++) {
            int row = wid * 8 + rr;
            int node = nodeBase + row;
            if (node >= NN) node = NN - 1;
            float4 acc = __ldg(&h4[node * 32 + lane]);
            int beg = g_rowptr[node];
            int end = g_rowptr[node + 1];
            int j = beg;
            for (; j + 4 <= end; j += 4) {
                int s0 = g_esorted[j];
                int s1 = g_esorted[j + 1];
                int s2 = g_esorted[j + 2];
                int s3 = g_esorted[j + 3];
                float4 v0 = __ldg(&h4[s0 * 32 + lane]);
                float4 v1 = __ldg(&h4[s1 * 32 + lane]);
                float4 v2 = __ldg(&h4[s2 * 32 + lane]);
                float4 v3 = __ldg(&h4[s3 * 32 + lane]);
                acc.x += (v0.x + v1.x) + (v2.x + v3.x);
                acc.y += (v0.y + v1.y) + (v2.y + v3.y);
                acc.z += (v0.z + v1.z) + (v2.z + v3.z);
                acc.w += (v0.w + v1.w) + (v2.w + v3.w);
            }
            for (; j < end; j++) {
                int s = g_esorted[j];
                float4 v = __ldg(&h4[s * 32 + lane]);
                acc.x += v.x; acc.y += v.y; acc.z += v.z; acc.w += v.w;
            }
            int col = lane * 4;
            store_hilo(pAhi, pAlo, row, col,     acc.x, acc.y);
            store_hilo(pAhi, pAlo, row, col + 2, acc.z, acc.w);
        }
    }
    __syncthreads();

    uint32_t aHi = smem_u32(pAhi), aLo = smem_u32(pAlo);
    uint32_t wHi = smem_u32(pWhi), wLo = smem_u32(pWlo);
    int mbase = (wid & 3) * 16;
    int nhalf = wid >> 2;
    int rbase = mbase + (lane >> 2);

    float c[8][4];
    // ---- MMA stage 1 ----
    mma_stage(aHi, aLo, wHi, wLo, mbase, nhalf, lane, c);
    __syncthreads();   // everyone done reading sA / sW

    // ---- epilogue 1: relu(C + b1) -> bf16 hi/lo back into A tiles ----
    #pragma unroll
    for (int nt = 0; nt < 8; nt++) {
        int col = nhalf * 64 + nt * 8 + (lane & 3) * 2;
        float2 bb = *(const float2*)&b1[col];
        float f0 = fmaxf(c[nt][0] + bb.x, 0.f);
        float f1 = fmaxf(c[nt][1] + bb.y, 0.f);
        float f2 = fmaxf(c[nt][2] + bb.x, 0.f);
        float f3 = fmaxf(c[nt][3] + bb.y, 0.f);
        store_hilo(pAhi, pAlo, rbase,     col, f0, f1);
        store_hilo(pAhi, pAlo, rbase + 8, col, f2, f3);
    }

    // ---- stage W2 into the same W buffers (same barrier window) ----
    {
        const float4* sh = (const float4*)g_whi[widx + 1];
        const float4* sl = (const float4*)g_wlo[widx + 1];
        float4* dh = (float4*)pWhi;
        float4* dl = (float4*)pWlo;
        #pragma unroll
        for (int i = 0; i < 8; i++) {
            int j = tid + 256 * i;
            dh[j] = sh[j];
            dl[j] = sl[j];
        }
    }
    __syncthreads();

    // ---- MMA stage 2 ----
    mma_stage(aHi, aLo, wHi, wLo, mbase, nhalf, lane, c);

    // ---- epilogue 2: C + b2 (+relu) -> fp32 gmem ----
    #pragma unroll
    for (int nt = 0; nt < 8; nt++) {
        int col = nhalf * 64 + nt * 8 + (lane & 3) * 2;
        float2 bb = *(const float2*)&b2[col];
        float v0 = c[nt][0] + bb.x;
        float v1 = c[nt][1] + bb.y;
        float v2 = c[nt][2] + bb.x;
        float v3 = c[nt][3] + bb.y;
        if (relu2) {
            v0 = fmaxf(v0, 0.f); v1 = fmaxf(v1, 0.f);
            v2 = fmaxf(v2, 0.f); v3 = fmaxf(v3, 0.f);
        }
        int n0 = nodeBase + rbase;
        int n1 = n0 + 8;
        if (n0 < NN) *(float2*)&hout[n0 * DD + col] = make_float2(v0, v1);
        if (n1 < NN) *(float2*)&hout[n1 * DD + col] = make_float2(v2, v3);
    }
}

// ---------------- mean pool over sorted batch --------------------------------
__device__ __forceinline__ int lbound_batch(const void* b, int val) {
    int lo = 0, hi = NN;
    if (g_idx64) {
        const long long* p = (const long long*)b;
        long long v = val;
        while (lo < hi) { int mid = (lo + hi) >> 1; if (p[mid] < v) lo = mid + 1; else hi = mid; }
    } else {
        const int* p = (const int*)b;
        while (lo < hi) { int mid = (lo + hi) >> 1; if (p[mid] < val) lo = mid + 1; else hi = mid; }
    }
    return lo;
}

__global__ void pool_kernel(const float* __restrict__ h,
                            const void* __restrict__ batch,
                            float* __restrict__ out) {
    int g = blockIdx.x;
    int d = threadIdx.x & 127;
    int sub = threadIdx.x >> 7;
    int start = lbound_batch(batch, g);
    int end   = lbound_batch(batch, g + 1);
    float acc = 0.f;
    for (int n = start + sub; n < end; n += 4)
        acc += h[n * DD + d];
    __shared__ float red[512];
    red[threadIdx.x] = acc;
    __syncthreads();
    if (sub == 0) {
        float s = (red[d] + red[d + 128]) + (red[d + 256] + red[d + 384]);
        int cnt = end - start;
        out[g * DD + d] = s / (float)(cnt > 0 ? cnt : 1);
    }
}

// ---------------- launch ------------------------------------------------------
extern "C" void kernel_launch(void* const* d_in, const int* in_sizes, int n_in,
                              void* d_out, int out_size) {
    const float* x = (const float*)d_in[0];
    const void* ei = d_in[1];
    const void* batch = d_in[2];
    const float *W1[3], *b1[3], *W2[3], *b2[3];
    for (int l = 0; l < 3; l++) {
        W1[l] = (const float*)d_in[3 + 4 * l];
        b1[l] = (const float*)d_in[4 + 4 * l];
        W2[l] = (const float*)d_in[5 + 4 * l];
        b2[l] = (const float*)d_in[6 + 4 * l];
    }
    float* out = (float*)d_out;

    cudaFuncSetAttribute(layer_kernel,
                         cudaFuncAttributeMaxDynamicSharedMemorySize, 98304);

    float *tmp, *h;
    cudaGetSymbolAddress((void**)&tmp, g_tmp);
    cudaGetSymbolAddress((void**)&h, g_h);

    detect_kernel<<<1, 1>>>(ei);
    zero_deg_kernel<<<(NN + 255) / 256, 256>>>();
    hist_kernel<<<(NE + 255) / 256, 256>>>(ei);
    reduce_kernel<<<SCAN_NB, SCAN_B>>>();
    partscan_kernel<<<1, 256>>>();
    localscan_kernel<<<SCAN_NB, SCAN_B>>>();
    fill_kernel<<<(NE + 255) / 256, 256>>>(ei);
    prep_kernel<<<6, 256>>>(W1[0], W2[0], W1[1], W2[1], W1[2], W2[2]);

    const int layer_blocks = (NN + 63) / 64;   // 1563
    layer_kernel<<<layer_blocks, 256, 98304>>>(x,   b1[0], b2[0], h,   0, 1);
    layer_kernel<<<layer_blocks, 256, 98304>>>(h,   b1[1], b2[1], tmp, 2, 1);
    layer_kernel<<<layer_blocks, 256, 98304>>>(tmp, b1[2], b2[2], h,   4, 0);

    pool_kernel<<<NG, 512>>>(h, batch, out);
}

// round 5
// speedup vs baseline: 2.0724x; 1.0213x over previous
#include <cuda_runtime.h>
#include <cuda_bf16.h>
#include <cstdint>

#define NN 100000
#define NE 1600000
#define DD 128
#define NG 128
#define NB 196            // scan blocks: 196*512 >= NN

// ---------------- scratch (static device globals; zero-initialized) ---------
__device__ __align__(16) float g_tmp[NN * DD];
__device__ __align__(16) float g_h[NN * DD];
__device__ int g_deg[NN];                 // zero at load; re-zeroed by cleanup
__device__ int g_rowptr[NN + 1];
__device__ int g_cursor[NN];
__device__ int g_esorted[NE];
__device__ unsigned long long g_desc[NB]; // lookback descriptors; zero/INVALID
// pre-transposed, pre-swizzled bf16 hi/lo weights {W1_0,W2_0,W1_1,W2_1,W1_2,W2_2}
__device__ __align__(16) __nv_bfloat16 g_whi[6][16384];
__device__ __align__(16) __nv_bfloat16 g_wlo[6][16384];

// ---------------- inline index-width detection ------------------------------
// edge values uniform in [0,100000): if int64, odd 32-bit words are all zero.
__device__ __forceinline__ int detect64(const void* p) {
    const unsigned* w = (const unsigned*)p;
    unsigned acc = 0;
    #pragma unroll
    for (int i = 0; i < 16; i++) acc |= w[2 * i + 1];
    return acc == 0u;
}

// ---------------- launch 0: weight prep (blocks 0-5) + degree hist ----------
__device__ __forceinline__ uint32_t w_off(int n, int k) {
    return (uint32_t)(n * 128 + (((k >> 3) ^ (n & 7)) << 3) + (k & 7));
}

__global__ void __launch_bounds__(512) pre_kernel(
        const void* __restrict__ ei,
        const float* w0, const float* w1, const float* w2,
        const float* w3, const float* w4, const float* w5) {
    if (blockIdx.x < 6) {
        const float* src[6] = {w0, w1, w2, w3, w4, w5};
        const float* W = src[blockIdx.x];
        for (int i = threadIdx.x; i < 16384; i += 512) {
            int k = i >> 7, n = i & 127;
            float v = W[i];
            __nv_bfloat16 hi = __float2bfloat16(v);
            __nv_bfloat16 lo = __float2bfloat16(v - __bfloat162float(hi));
            uint32_t idx = w_off(n, k);
            g_whi[blockIdx.x][idx] = hi;
            g_wlo[blockIdx.x][idx] = lo;
        }
        return;
    }
    __shared__ int s_is64;
    if (threadIdx.x == 0) s_is64 = detect64(ei);
    __syncthreads();
    int e = (blockIdx.x - 6) * 512 + threadIdx.x;   // grid sized exactly
    int dst = s_is64 ? (int)((const long long*)ei)[(long)NE + e]
                     : ((const int*)ei)[NE + e];
    atomicAdd(&g_deg[dst], 1);
}

// ---------------- launch 1: single-kernel exclusive scan (lookback) ---------
__global__ void __launch_bounds__(512) scan_kernel() {
    int b = blockIdx.x, t = threadIdx.x;
    int idx = b * 512 + t;
    int v = (idx < NN) ? g_deg[idx] : 0;
    int lane = t & 31, w = t >> 5;
    int x = v;
    #pragma unroll
    for (int o = 1; o < 32; o <<= 1) {
        int u = __shfl_up_sync(~0u, x, o);
        if (lane >= o) x += u;
    }
    __shared__ int ws[16], wo[16];
    __shared__ int s_prefix, s_total;
    if (lane == 31) ws[w] = x;
    __syncthreads();
    if (t < 16) {
        int y = ws[t], z = y;
        #pragma unroll
        for (int o = 1; o < 16; o <<= 1) {
            int u = __shfl_up_sync(0xffffu, z, o, 16);
            if (t >= o) z += u;
        }
        wo[t] = z - y;
        if (t == 15) s_total = z;
    }
    __syncthreads();
    int incl = x + wo[w];
    if (t == 0) {
        int total = s_total;
        atomicExch(&g_desc[b], (1ULL << 32) | (unsigned)total);   // AGGREGATE
        long long running = 0;
        for (int i = b - 1; i >= 0;) {
            unsigned long long d;
            do { d = atomicAdd(&g_desc[i], 0ULL); } while ((d >> 32) == 0ULL);
            running += (unsigned)d;
            if ((d >> 32) == 2ULL) break;   // PREFIX: includes all <= i
            i--;
        }
        s_prefix = (int)running;
        atomicExch(&g_desc[b], (2ULL << 32) | (unsigned)(running + total));
    }
    __syncthreads();
    int excl = s_prefix + incl - v;
    if (idx < NN) { g_rowptr[idx] = excl; g_cursor[idx] = excl; }
    if (idx == NN - 1) g_rowptr[NN] = s_prefix + incl;
}

// ---------------- launch 2: CSR fill ----------------------------------------
__global__ void __launch_bounds__(512) fill_kernel(const void* __restrict__ ei) {
    __shared__ int s_is64;
    if (threadIdx.x == 0) s_is64 = detect64(ei);
    __syncthreads();
    int e = blockIdx.x * 512 + threadIdx.x;   // grid exact
    int dst, src;
    if (s_is64) {
        dst = (int)((const long long*)ei)[(long)NE + e];
        src = (int)((const long long*)ei)[e];
    } else {
        dst = ((const int*)ei)[NE + e];
        src = ((const int*)ei)[e];
    }
    int pos = atomicAdd(&g_cursor[dst], 1);
    g_esorted[pos] = src;
}

// ---------------- warp-MMA helpers ------------------------------------------
__device__ __forceinline__ uint32_t smem_u32(const void* p) {
    uint32_t a;
    asm("{ .reg .u64 t; cvta.to.shared.u64 t, %1; cvt.u32.u64 %0, t; }"
        : "=r"(a) : "l"(p));
    return a;
}
__device__ __forceinline__ void ldsm4(unsigned r[4], uint32_t addr) {
    asm volatile("ldmatrix.sync.aligned.m8n8.x4.shared.b16 {%0,%1,%2,%3}, [%4];"
                 : "=r"(r[0]), "=r"(r[1]), "=r"(r[2]), "=r"(r[3]) : "r"(addr));
}
__device__ __forceinline__ void mma16816(float c[4], const unsigned a[4],
                                         const unsigned b[2]) {
    asm volatile(
        "mma.sync.aligned.m16n8k16.row.col.f32.bf16.bf16.f32 "
        "{%0,%1,%2,%3}, {%4,%5,%6,%7}, {%8,%9}, {%0,%1,%2,%3};"
        : "+f"(c[0]), "+f"(c[1]), "+f"(c[2]), "+f"(c[3])
        : "r"(a[0]), "r"(a[1]), "r"(a[2]), "r"(a[3]), "r"(b[0]), "r"(b[1]));
}

// 64x128 @ 128x128 stage; warp = 32 rows x 32 cols (2 m-tiles x 4 n-tiles)
__device__ __forceinline__ void mma_stage(uint32_t aHi, uint32_t aLo,
                                          uint32_t wHi, uint32_t wLo,
                                          int mhalf, int nq, int lane,
                                          float c[2][4][4]) {
    #pragma unroll
    for (int mt = 0; mt < 2; mt++)
        #pragma unroll
        for (int nt = 0; nt < 4; nt++)
            #pragma unroll
            for (int q = 0; q < 4; q++) c[mt][nt][q] = 0.f;

    int m = lane >> 3, r = lane & 7;
    uint32_t aRow[2], bRow[2];
    #pragma unroll
    for (int mt = 0; mt < 2; mt++)
        aRow[mt] = (uint32_t)(mhalf * 32 + mt * 16 + (m & 1) * 8 + r) * 256;
    #pragma unroll
    for (int bt = 0; bt < 2; bt++)
        bRow[bt] = (uint32_t)(nq * 32 + bt * 16 + (m >> 1) * 8 + r) * 256;
    int aAdd = m >> 1, bAdd = m & 1;

    #pragma unroll
    for (int k = 0; k < 8; k++) {
        unsigned ah[2][4], al[2][4], bh[2][4], bl[2][4];
        uint32_t ac = (uint32_t)(((k * 2 + aAdd) ^ r) << 4);
        uint32_t bc = (uint32_t)(((k * 2 + bAdd) ^ r) << 4);
        #pragma unroll
        for (int mt = 0; mt < 2; mt++) {
            ldsm4(ah[mt], aHi + aRow[mt] + ac);
            ldsm4(al[mt], aLo + aRow[mt] + ac);
        }
        #pragma unroll
        for (int bt = 0; bt < 2; bt++) {
            ldsm4(bh[bt], wHi + bRow[bt] + bc);
            ldsm4(bl[bt], wLo + bRow[bt] + bc);
        }
        #pragma unroll
        for (int mt = 0; mt < 2; mt++)
            #pragma unroll
            for (int nt = 0; nt < 4; nt++) {
                const unsigned* BH = bh[nt >> 1] + (nt & 1) * 2;
                const unsigned* BL = bl[nt >> 1] + (nt & 1) * 2;
                mma16816(c[mt][nt], ah[mt], BH);
                mma16816(c[mt][nt], al[mt], BH);
                mma16816(c[mt][nt], ah[mt], BL);
            }
    }
}

__device__ __forceinline__ void store_hilo(char* pH, char* pL, int row, int col,
                                           float f0, float f1) {
    __nv_bfloat16 h0 = __float2bfloat16(f0), h1 = __float2bfloat16(f1);
    __nv_bfloat16 l0 = __float2bfloat16(f0 - __bfloat162float(h0));
    __nv_bfloat16 l1 = __float2bfloat16(f1 - __bfloat162float(h1));
    uint32_t off = (uint32_t)(row * 256 + (((col >> 3) ^ (row & 7)) << 4)
                              + (col & 7) * 2);
    *(__nv_bfloat162*)(pH + off) = __halves2bfloat162(h0, h1);
    *(__nv_bfloat162*)(pL + off) = __halves2bfloat162(l0, l1);
}

__device__ __forceinline__ void stcs2(float* p, float v0, float v1) {
    asm volatile("st.global.cs.v2.f32 [%0], {%1,%2};" :: "l"(p), "f"(v0), "f"(v1)
                 : "memory");
}

// ---------------- fused layer: gather -> MMA1 -> relu -> MMA2 ---------------
// 256 threads, 64-row tile, 96KB smem -> 2 CTAs/SM.
__global__ void __launch_bounds__(256, 2) layer_kernel(
        const float* __restrict__ hin,
        const float* __restrict__ b1, const float* __restrict__ b2,
        float* __restrict__ hout, int widx, int relu2) {
    extern __shared__ char smem[];
    char* pAhi = smem;             // 64 x 256B = 16KB
    char* pAlo = smem + 16384;
    char* pWhi = smem + 32768;     // 128 x 256B = 32KB
    char* pWlo = smem + 65536;

    int tid = threadIdx.x;
    int lane = tid & 31, wid = tid >> 5;
    int nodeBase = blockIdx.x * 64;

    // ---- stage W1 ----
    {
        const float4* sh = (const float4*)g_whi[widx];
        const float4* sl = (const float4*)g_wlo[widx];
        float4* dh = (float4*)pWhi;
        float4* dl = (float4*)pWlo;
        #pragma unroll
        for (int i = 0; i < 8; i++) {
            int j = tid + 256 * i;
            dh[j] = sh[j];
            dl[j] = sl[j];
        }
    }

    // ---- gather: warp w -> rows w*8 .. w*8+7 ----
    {
        const float4* h4 = (const float4*)hin;
        #pragma unroll 1
        for (int rr = 0; rr < 8; rr++) {
            int row = wid * 8 + rr;
            int node = nodeBase + row;
            if (node >= NN) node = NN - 1;
            float4 acc = __ldg(&h4[node * 32 + lane]);
            int beg = g_rowptr[node];
            int end = g_rowptr[node + 1];
            int j = beg;
            for (; j + 8 <= end; j += 8) {
                int s0 = g_esorted[j],     s1 = g_esorted[j + 1];
                int s2 = g_esorted[j + 2], s3 = g_esorted[j + 3];
                int s4 = g_esorted[j + 4], s5 = g_esorted[j + 5];
                int s6 = g_esorted[j + 6], s7 = g_esorted[j + 7];
                float4 v0 = __ldg(&h4[s0 * 32 + lane]);
                float4 v1 = __ldg(&h4[s1 * 32 + lane]);
                float4 v2 = __ldg(&h4[s2 * 32 + lane]);
                float4 v3 = __ldg(&h4[s3 * 32 + lane]);
                float4 v4 = __ldg(&h4[s4 * 32 + lane]);
                float4 v5 = __ldg(&h4[s5 * 32 + lane]);
                float4 v6 = __ldg(&h4[s6 * 32 + lane]);
                float4 v7 = __ldg(&h4[s7 * 32 + lane]);
                acc.x += ((v0.x + v1.x) + (v2.x + v3.x)) + ((v4.x + v5.x) + (v6.x + v7.x));
                acc.y += ((v0.y + v1.y) + (v2.y + v3.y)) + ((v4.y + v5.y) + (v6.y + v7.y));
                acc.z += ((v0.z + v1.z) + (v2.z + v3.z)) + ((v4.z + v5.z) + (v6.z + v7.z));
                acc.w += ((v0.w + v1.w) + (v2.w + v3.w)) + ((v4.w + v5.w) + (v6.w + v7.w));
            }
            if (j + 4 <= end) {
                int s0 = g_esorted[j],     s1 = g_esorted[j + 1];
                int s2 = g_esorted[j + 2], s3 = g_esorted[j + 3];
                float4 v0 = __ldg(&h4[s0 * 32 + lane]);
                float4 v1 = __ldg(&h4[s1 * 32 + lane]);
                float4 v2 = __ldg(&h4[s2 * 32 + lane]);
                float4 v3 = __ldg(&h4[s3 * 32 + lane]);
                acc.x += (v0.x + v1.x) + (v2.x + v3.x);
                acc.y += (v0.y + v1.y) + (v2.y + v3.y);
                acc.z += (v0.z + v1.z) + (v2.z + v3.z);
                acc.w += (v0.w + v1.w) + (v2.w + v3.w);
                j += 4;
            }
            for (; j < end; j++) {
                int s = g_esorted[j];
                float4 v = __ldg(&h4[s * 32 + lane]);
                acc.x += v.x; acc.y += v.y; acc.z += v.z; acc.w += v.w;
            }
            int col = lane * 4;
            store_hilo(pAhi, pAlo, row, col,     acc.x, acc.y);
            store_hilo(pAhi, pAlo, row, col + 2, acc.z, acc.w);
        }
    }
    __syncthreads();

    uint32_t aHi = smem_u32(pAhi), aLo = smem_u32(pAlo);
    uint32_t wHi = smem_u32(pWhi), wLo = smem_u32(pWlo);
    int mhalf = wid & 1;
    int nq = wid >> 1;
    int gid = lane >> 2, lc = (lane & 3) * 2;

    float c[2][4][4];
    // ---- MMA stage 1 ----
    mma_stage(aHi, aLo, wHi, wLo, mhalf, nq, lane, c);
    __syncthreads();

    // ---- epilogue 1: relu(C+b1) -> bf16 hi/lo into A tiles ----
    #pragma unroll
    for (int mt = 0; mt < 2; mt++)
        #pragma unroll
        for (int nt = 0; nt < 4; nt++) {
            int col = nq * 32 + nt * 8 + lc;
            float2 bb = *(const float2*)&b1[col];
            int r0 = mhalf * 32 + mt * 16 + gid;
            float f0 = fmaxf(c[mt][nt][0] + bb.x, 0.f);
            float f1 = fmaxf(c[mt][nt][1] + bb.y, 0.f);
            float f2 = fmaxf(c[mt][nt][2] + bb.x, 0.f);
            float f3 = fmaxf(c[mt][nt][3] + bb.y, 0.f);
            store_hilo(pAhi, pAlo, r0,     col, f0, f1);
            store_hilo(pAhi, pAlo, r0 + 8, col, f2, f3);
        }

    // ---- stage W2 into same buffers ----
    {
        const float4* sh = (const float4*)g_whi[widx + 1];
        const float4* sl = (const float4*)g_wlo[widx + 1];
        float4* dh = (float4*)pWhi;
        float4* dl = (float4*)pWlo;
        #pragma unroll
        for (int i = 0; i < 8; i++) {
            int j = tid + 256 * i;
            dh[j] = sh[j];
            dl[j] = sl[j];
        }
    }
    __syncthreads();

    // ---- MMA stage 2 ----
    mma_stage(aHi, aLo, wHi, wLo, mhalf, nq, lane, c);

    // ---- epilogue 2: C + b2 (+relu) -> gmem (streaming stores) ----
    #pragma unroll
    for (int mt = 0; mt < 2; mt++)
        #pragma unroll
        for (int nt = 0; nt < 4; nt++) {
            int col = nq * 32 + nt * 8 + lc;
            float2 bb = *(const float2*)&b2[col];
            float v0 = c[mt][nt][0] + bb.x;
            float v1 = c[mt][nt][1] + bb.y;
            float v2 = c[mt][nt][2] + bb.x;
            float v3 = c[mt][nt][3] + bb.y;
            if (relu2) {
                v0 = fmaxf(v0, 0.f); v1 = fmaxf(v1, 0.f);
                v2 = fmaxf(v2, 0.f); v3 = fmaxf(v3, 0.f);
            }
            int r0 = mhalf * 32 + mt * 16 + gid;
            int n0 = nodeBase + r0;
            int n1 = n0 + 8;
            if (n0 < NN) stcs2(&hout[n0 * DD + col], v0, v1);
            if (n1 < NN) stcs2(&hout[n1 * DD + col], v2, v3);
        }
}

// ---------------- mean pool over sorted batch --------------------------------
__device__ __forceinline__ int lbound_batch(const void* b, int val, int is64) {
    int lo = 0, hi = NN;
    if (is64) {
        const long long* p = (const long long*)b;
        long long v = val;
        while (lo < hi) { int mid = (lo + hi) >> 1; if (p[mid] < v) lo = mid + 1; else hi = mid; }
    } else {
        const int* p = (const int*)b;
        while (lo < hi) { int mid = (lo + hi) >> 1; if (p[mid] < val) lo = mid + 1; else hi = mid; }
    }
    return lo;
}

__global__ void pool_kernel(const float* __restrict__ h,
                            const void* __restrict__ batch,
                            const void* __restrict__ ei,
                            float* __restrict__ out) {
    __shared__ int s_is64;
    if (threadIdx.x == 0) s_is64 = detect64(ei);
    __syncthreads();
    int g = blockIdx.x;
    int d = threadIdx.x & 127;
    int sub = threadIdx.x >> 7;
    int start = lbound_batch(batch, g, s_is64);
    int end   = lbound_batch(batch, g + 1, s_is64);
    float acc = 0.f;
    for (int n = start + sub; n < end; n += 4)
        acc += h[n * DD + d];
    __shared__ float red[512];
    red[threadIdx.x] = acc;
    __syncthreads();
    if (sub == 0) {
        float s = (red[d] + red[d + 128]) + (red[d + 256] + red[d + 384]);
        int cnt = end - start;
        out[g * DD + d] = s / (float)(cnt > 0 ? cnt : 1);
    }
}

// ---------------- launch N+1: restore invariants for next call ---------------
__global__ void __launch_bounds__(512) cleanup_kernel() {
    int idx = blockIdx.x * 512 + threadIdx.x;
    if (idx < NN) g_deg[idx] = 0;
    if (idx < NB) g_desc[idx] = 0ULL;
}

// ---------------- launch ------------------------------------------------------
extern "C" void kernel_launch(void* const* d_in, const int* in_sizes, int n_in,
                              void* d_out, int out_size) {
    const float* x = (const float*)d_in[0];
    const void* ei = d_in[1];
    const void* batch = d_in[2];
    const float *W1[3], *b1[3], *W2[3], *b2[3];
    for (int l = 0; l < 3; l++) {
        W1[l] = (const float*)d_in[3 + 4 * l];
        b1[l] = (const float*)d_in[4 + 4 * l];
        W2[l] = (const float*)d_in[5 + 4 * l];
        b2[l] = (const float*)d_in[6 + 4 * l];
    }
    float* out = (float*)d_out;

    cudaFuncSetAttribute(layer_kernel,
                         cudaFuncAttributeMaxDynamicSharedMemorySize, 98304);

    float *tmp, *h;
    cudaGetSymbolAddress((void**)&tmp, g_tmp);
    cudaGetSymbolAddress((void**)&h, g_h);

    // NE == 3125 * 512 exactly; grids below are exact (no bounds checks needed)
    pre_kernel<<<6 + NE / 512, 512>>>(ei, W1[0], W2[0], W1[1], W2[1], W1[2], W2[2]); // 0
    scan_kernel<<<NB, 512>>>();                                                       // 1
    fill_kernel<<<NE / 512, 512>>>(ei);                                               // 2

    const int layer_blocks = (NN + 63) / 64;   // 1563
    layer_kernel<<<layer_blocks, 256, 98304>>>(x,   b1[0], b2[0], h,   0, 1);         // 3 (profiled)
    layer_kernel<<<layer_blocks, 256, 98304>>>(h,   b1[1], b2[1], tmp, 2, 1);         // 4
    layer_kernel<<<layer_blocks, 256, 98304>>>(tmp, b1[2], b2[2], h,   4, 0);         // 5

    pool_kernel<<<NG, 512>>>(h, batch, ei, out);                                      // 6
    cleanup_kernel<<<NB, 512>>>();                                                    // 7
}

// round 6
// speedup vs baseline: 2.1470x; 1.0360x over previous
#include <cuda_runtime.h>
#include <cuda_bf16.h>
#include <cstdint>

#define NN 100000
#define NE 1600000
#define DD 128
#define NG 128
#define NB 196            // scan blocks: 196*512 >= NN

// ---------------- scratch (static device globals; zero-initialized) ---------
__device__ __align__(16) float g_tmp[NN * DD];
__device__ __align__(16) float g_h[NN * DD];
__device__ int g_deg[NN];                 // zero at load; re-zeroed by cleanup
__device__ int g_rowptr[NN + 1];
__device__ int g_cursor[NN];
__device__ int g_esorted[NE];
__device__ unsigned long long g_desc[NB]; // lookback descriptors; zero/INVALID
// pre-transposed, pre-swizzled bf16 hi/lo weights {W1_0,W2_0,W1_1,W2_1,W1_2,W2_2}
__device__ __align__(16) __nv_bfloat16 g_whi[6][16384];
__device__ __align__(16) __nv_bfloat16 g_wlo[6][16384];

// ---------------- inline index-width detection ------------------------------
__device__ __forceinline__ int detect64(const void* p) {
    const unsigned* w = (const unsigned*)p;
    unsigned acc = 0;
    #pragma unroll
    for (int i = 0; i < 16; i++) acc |= w[2 * i + 1];
    return acc == 0u;
}

// ---------------- launch 0: weight prep (blocks 0-5) + degree hist ----------
__device__ __forceinline__ uint32_t w_off(int n, int k) {
    return (uint32_t)(n * 128 + (((k >> 3) ^ (n & 7)) << 3) + (k & 7));
}

__global__ void __launch_bounds__(512) pre_kernel(
        const void* __restrict__ ei,
        const float* w0, const float* w1, const float* w2,
        const float* w3, const float* w4, const float* w5) {
    if (blockIdx.x < 6) {
        const float* src[6] = {w0, w1, w2, w3, w4, w5};
        const float* W = src[blockIdx.x];
        for (int i = threadIdx.x; i < 16384; i += 512) {
            int k = i >> 7, n = i & 127;
            float v = W[i];
            __nv_bfloat16 hi = __float2bfloat16(v);
            __nv_bfloat16 lo = __float2bfloat16(v - __bfloat162float(hi));
            uint32_t idx = w_off(n, k);
            g_whi[blockIdx.x][idx] = hi;
            g_wlo[blockIdx.x][idx] = lo;
        }
        return;
    }
    __shared__ int s_is64;
    if (threadIdx.x == 0) s_is64 = detect64(ei);
    __syncthreads();
    int e = (blockIdx.x - 6) * 512 + threadIdx.x;   // grid sized exactly
    int dst = s_is64 ? (int)((const long long*)ei)[(long)NE + e]
                     : ((const int*)ei)[NE + e];
    atomicAdd(&g_deg[dst], 1);
}

// ---------------- launch 1: single-kernel exclusive scan (lookback) ---------
__global__ void __launch_bounds__(512) scan_kernel() {
    int b = blockIdx.x, t = threadIdx.x;
    int idx = b * 512 + t;
    int v = (idx < NN) ? g_deg[idx] : 0;
    int lane = t & 31, w = t >> 5;
    int x = v;
    #pragma unroll
    for (int o = 1; o < 32; o <<= 1) {
        int u = __shfl_up_sync(~0u, x, o);
        if (lane >= o) x += u;
    }
    __shared__ int ws[16], wo[16];
    __shared__ int s_prefix, s_total;
    if (lane == 31) ws[w] = x;
    __syncthreads();
    if (t < 16) {
        int y = ws[t], z = y;
        #pragma unroll
        for (int o = 1; o < 16; o <<= 1) {
            int u = __shfl_up_sync(0xffffu, z, o, 16);
            if (t >= o) z += u;
        }
        wo[t] = z - y;
        if (t == 15) s_total = z;
    }
    __syncthreads();
    int incl = x + wo[w];
    if (t == 0) {
        int total = s_total;
        atomicExch(&g_desc[b], (1ULL << 32) | (unsigned)total);   // AGGREGATE
        long long running = 0;
        for (int i = b - 1; i >= 0;) {
            unsigned long long d;
            do { d = atomicAdd(&g_desc[i], 0ULL); } while ((d >> 32) == 0ULL);
            running += (unsigned)d;
            if ((d >> 32) == 2ULL) break;   // PREFIX
            i--;
        }
        s_prefix = (int)running;
        atomicExch(&g_desc[b], (2ULL << 32) | (unsigned)(running + total));
    }
    __syncthreads();
    int excl = s_prefix + incl - v;
    if (idx < NN) { g_rowptr[idx] = excl; g_cursor[idx] = excl; }
    if (idx == NN - 1) g_rowptr[NN] = s_prefix + incl;
}

// ---------------- launch 2: CSR fill ----------------------------------------
__global__ void __launch_bounds__(512) fill_kernel(const void* __restrict__ ei) {
    __shared__ int s_is64;
    if (threadIdx.x == 0) s_is64 = detect64(ei);
    __syncthreads();
    int e = blockIdx.x * 512 + threadIdx.x;   // grid exact
    int dst, src;
    if (s_is64) {
        dst = (int)((const long long*)ei)[(long)NE + e];
        src = (int)((const long long*)ei)[e];
    } else {
        dst = ((const int*)ei)[NE + e];
        src = ((const int*)ei)[e];
    }
    int pos = atomicAdd(&g_cursor[dst], 1);
    g_esorted[pos] = src;
}

// ---------------- warp-MMA helpers ------------------------------------------
__device__ __forceinline__ uint32_t smem_u32(const void* p) {
    uint32_t a;
    asm("{ .reg .u64 t; cvta.to.shared.u64 t, %1; cvt.u32.u64 %0, t; }"
        : "=r"(a) : "l"(p));
    return a;
}
__device__ __forceinline__ void ldsm4(unsigned r[4], uint32_t addr) {
    asm volatile("ldmatrix.sync.aligned.m8n8.x4.shared.b16 {%0,%1,%2,%3}, [%4];"
                 : "=r"(r[0]), "=r"(r[1]), "=r"(r[2]), "=r"(r[3]) : "r"(addr));
}
__device__ __forceinline__ void mma16816(float c[4], const unsigned a[4],
                                         const unsigned b[2]) {
    asm volatile(
        "mma.sync.aligned.m16n8k16.row.col.f32.bf16.bf16.f32 "
        "{%0,%1,%2,%3}, {%4,%5,%6,%7}, {%8,%9}, {%0,%1,%2,%3};"
        : "+f"(c[0]), "+f"(c[1]), "+f"(c[2]), "+f"(c[3])
        : "r"(a[0]), "r"(a[1]), "r"(a[2]), "r"(a[3]), "r"(b[0]), "r"(b[1]));
}

// 64x128 @ 128x128 stage; warp = 32 rows x 32 cols (2 m-tiles x 4 n-tiles)
__device__ __forceinline__ void mma_stage(uint32_t aHi, uint32_t aLo,
                                          uint32_t wHi, uint32_t wLo,
                                          int mhalf, int nq, int lane,
                                          float c[2][4][4]) {
    #pragma unroll
    for (int mt = 0; mt < 2; mt++)
        #pragma unroll
        for (int nt = 0; nt < 4; nt++)
            #pragma unroll
            for (int q = 0; q < 4; q++) c[mt][nt][q] = 0.f;

    int m = lane >> 3, r = lane & 7;
    uint32_t aRow[2], bRow[2];
    #pragma unroll
    for (int mt = 0; mt < 2; mt++)
        aRow[mt] = (uint32_t)(mhalf * 32 + mt * 16 + (m & 1) * 8 + r) * 256;
    #pragma unroll
    for (int bt = 0; bt < 2; bt++)
        bRow[bt] = (uint32_t)(nq * 32 + bt * 16 + (m >> 1) * 8 + r) * 256;
    int aAdd = m >> 1, bAdd = m & 1;

    #pragma unroll
    for (int k = 0; k < 8; k++) {
        unsigned ah[2][4], al[2][4], bh[2][4], bl[2][4];
        uint32_t ac = (uint32_t)(((k * 2 + aAdd) ^ r) << 4);
        uint32_t bc = (uint32_t)(((k * 2 + bAdd) ^ r) << 4);
        #pragma unroll
        for (int mt = 0; mt < 2; mt++) {
            ldsm4(ah[mt], aHi + aRow[mt] + ac);
            ldsm4(al[mt], aLo + aRow[mt] + ac);
        }
        #pragma unroll
        for (int bt = 0; bt < 2; bt++) {
            ldsm4(bh[bt], wHi + bRow[bt] + bc);
            ldsm4(bl[bt], wLo + bRow[bt] + bc);
        }
        #pragma unroll
        for (int mt = 0; mt < 2; mt++)
            #pragma unroll
            for (int nt = 0; nt < 4; nt++) {
                const unsigned* BH = bh[nt >> 1] + (nt & 1) * 2;
                const unsigned* BL = bl[nt >> 1] + (nt & 1) * 2;
                mma16816(c[mt][nt], ah[mt], BH);
                mma16816(c[mt][nt], al[mt], BH);
                mma16816(c[mt][nt], ah[mt], BL);
            }
    }
}

__device__ __forceinline__ void store_hilo(char* pH, char* pL, int row, int col,
                                           float f0, float f1) {
    __nv_bfloat16 h0 = __float2bfloat16(f0), h1 = __float2bfloat16(f1);
    __nv_bfloat16 l0 = __float2bfloat16(f0 - __bfloat162float(h0));
    __nv_bfloat16 l1 = __float2bfloat16(f1 - __bfloat162float(h1));
    uint32_t off = (uint32_t)(row * 256 + (((col >> 3) ^ (row & 7)) << 4)
                              + (col & 7) * 2);
    *(__nv_bfloat162*)(pH + off) = __halves2bfloat162(h0, h1);
    *(__nv_bfloat162*)(pL + off) = __halves2bfloat162(l0, l1);
}

__device__ __forceinline__ void stcs2(float* p, float v0, float v1) {
    asm volatile("st.global.cs.v2.f32 [%0], {%1,%2};" :: "l"(p), "f"(v0), "f"(v1)
                 : "memory");
}

// ---------------- fused layer: gather -> MMA1 -> relu -> MMA2 ---------------
// 256 threads, 64-row tile, 96KB smem -> 2 CTAs/SM.
__global__ void __launch_bounds__(256, 2) layer_kernel(
        const float* __restrict__ hin,
        const float* __restrict__ b1, const float* __restrict__ b2,
        float* __restrict__ hout, int widx, int relu2) {
    extern __shared__ char smem[];
    char* pAhi = smem;             // 64 x 256B = 16KB
    char* pAlo = smem + 16384;
    char* pWhi = smem + 32768;     // 128 x 256B = 32KB
    char* pWlo = smem + 65536;

    int tid = threadIdx.x;
    int lane = tid & 31, wid = tid >> 5;
    int nodeBase = blockIdx.x * 64;

    // ---- stage W1 ----
    {
        const float4* sh = (const float4*)g_whi[widx];
        const float4* sl = (const float4*)g_wlo[widx];
        float4* dh = (float4*)pWhi;
        float4* dl = (float4*)pWlo;
        #pragma unroll
        for (int i = 0; i < 8; i++) {
            int j = tid + 256 * i;
            dh[j] = sh[j];
            dl[j] = sl[j];
        }
    }

    // ---- gather: warp w -> rows w*8..w*8+7, processed as 4 interleaved pairs
    // Two independent dependency chains per warp + index prefetch so index
    // latency hides under data latency.
    {
        const float4* h4 = (const float4*)hin;
        const int* es = g_esorted;
        #pragma unroll 1
        for (int pr = 0; pr < 4; pr++) {
            int rowA = wid * 8 + pr * 2;
            int rowB = rowA + 1;
            int nodeA = nodeBase + rowA; if (nodeA >= NN) nodeA = NN - 1;
            int nodeB = nodeBase + rowB; if (nodeB >= NN) nodeB = NN - 1;
            float4 accA = __ldg(&h4[nodeA * 32 + lane]);
            float4 accB = __ldg(&h4[nodeB * 32 + lane]);
            int ja = g_rowptr[nodeA], ea = g_rowptr[nodeA + 1];
            int jb = g_rowptr[nodeB], eb = g_rowptr[nodeB + 1];

            int ia0, ia1, ia2, ia3, ib0, ib1, ib2, ib3;
            bool hA = (ja + 4 <= ea);
            bool hB = (jb + 4 <= eb);
            if (hA) {
                ia0 = __ldg(&es[ja]);     ia1 = __ldg(&es[ja + 1]);
                ia2 = __ldg(&es[ja + 2]); ia3 = __ldg(&es[ja + 3]);
            }
            if (hB) {
                ib0 = __ldg(&es[jb]);     ib1 = __ldg(&es[jb + 1]);
                ib2 = __ldg(&es[jb + 2]); ib3 = __ldg(&es[jb + 3]);
            }
            #pragma unroll 1
            while (hA || hB) {
                float4 va0, va1, va2, va3, vb0, vb1, vb2, vb3;
                if (hA) {
                    va0 = __ldg(&h4[ia0 * 32 + lane]);
                    va1 = __ldg(&h4[ia1 * 32 + lane]);
                    va2 = __ldg(&h4[ia2 * 32 + lane]);
                    va3 = __ldg(&h4[ia3 * 32 + lane]);
                }
                if (hB) {
                    vb0 = __ldg(&h4[ib0 * 32 + lane]);
                    vb1 = __ldg(&h4[ib1 * 32 + lane]);
                    vb2 = __ldg(&h4[ib2 * 32 + lane]);
                    vb3 = __ldg(&h4[ib3 * 32 + lane]);
                }
                // prefetch next index batches (independent of data loads)
                bool nA = hA && (ja + 8 <= ea);
                bool nB = hB && (jb + 8 <= eb);
                int xa0, xa1, xa2, xa3, xb0, xb1, xb2, xb3;
                if (nA) {
                    xa0 = __ldg(&es[ja + 4]); xa1 = __ldg(&es[ja + 5]);
                    xa2 = __ldg(&es[ja + 6]); xa3 = __ldg(&es[ja + 7]);
                }
                if (nB) {
                    xb0 = __ldg(&es[jb + 4]); xb1 = __ldg(&es[jb + 5]);
                    xb2 = __ldg(&es[jb + 6]); xb3 = __ldg(&es[jb + 7]);
                }
                if (hA) {
                    accA.x += (va0.x + va1.x) + (va2.x + va3.x);
                    accA.y += (va0.y + va1.y) + (va2.y + va3.y);
                    accA.z += (va0.z + va1.z) + (va2.z + va3.z);
                    accA.w += (va0.w + va1.w) + (va2.w + va3.w);
                    ja += 4;
                }
                if (hB) {
                    accB.x += (vb0.x + vb1.x) + (vb2.x + vb3.x);
                    accB.y += (vb0.y + vb1.y) + (vb2.y + vb3.y);
                    accB.z += (vb0.z + vb1.z) + (vb2.z + vb3.z);
                    accB.w += (vb0.w + vb1.w) + (vb2.w + vb3.w);
                    jb += 4;
                }
                if (nA) { ia0 = xa0; ia1 = xa1; ia2 = xa2; ia3 = xa3; }
                if (nB) { ib0 = xb0; ib1 = xb1; ib2 = xb2; ib3 = xb3; }
                hA = nA; hB = nB;
            }
            // drain remainders (<4 edges per row)
            for (; ja < ea; ja++) {
                int s = __ldg(&es[ja]);
                float4 v = __ldg(&h4[s * 32 + lane]);
                accA.x += v.x; accA.y += v.y; accA.z += v.z; accA.w += v.w;
            }
            for (; jb < eb; jb++) {
                int s = __ldg(&es[jb]);
                float4 v = __ldg(&h4[s * 32 + lane]);
                accB.x += v.x; accB.y += v.y; accB.z += v.z; accB.w += v.w;
            }
            int col = lane * 4;
            store_hilo(pAhi, pAlo, rowA, col,     accA.x, accA.y);
            store_hilo(pAhi, pAlo, rowA, col + 2, accA.z, accA.w);
            store_hilo(pAhi, pAlo, rowB, col,     accB.x, accB.y);
            store_hilo(pAhi, pAlo, rowB, col + 2, accB.z, accB.w);
        }
    }
    __syncthreads();

    uint32_t aHi = smem_u32(pAhi), aLo = smem_u32(pAlo);
    uint32_t wHi = smem_u32(pWhi), wLo = smem_u32(pWlo);
    int mhalf = wid & 1;
    int nq = wid >> 1;
    int gid = lane >> 2, lc = (lane & 3) * 2;

    float c[2][4][4];
    // ---- MMA stage 1 ----
    mma_stage(aHi, aLo, wHi, wLo, mhalf, nq, lane, c);
    __syncthreads();

    // ---- epilogue 1: relu(C+b1) -> bf16 hi/lo into A tiles ----
    #pragma unroll
    for (int mt = 0; mt < 2; mt++)
        #pragma unroll
        for (int nt = 0; nt < 4; nt++) {
            int col = nq * 32 + nt * 8 + lc;
            float2 bb = *(const float2*)&b1[col];
            int r0 = mhalf * 32 + mt * 16 + gid;
            float f0 = fmaxf(c[mt][nt][0] + bb.x, 0.f);
            float f1 = fmaxf(c[mt][nt][1] + bb.y, 0.f);
            float f2 = fmaxf(c[mt][nt][2] + bb.x, 0.f);
            float f3 = fmaxf(c[mt][nt][3] + bb.y, 0.f);
            store_hilo(pAhi, pAlo, r0,     col, f0, f1);
            store_hilo(pAhi, pAlo, r0 + 8, col, f2, f3);
        }

    // ---- stage W2 into same buffers ----
    {
        const float4* sh = (const float4*)g_whi[widx + 1];
        const float4* sl = (const float4*)g_wlo[widx + 1];
        float4* dh = (float4*)pWhi;
        float4* dl = (float4*)pWlo;
        #pragma unroll
        for (int i = 0; i < 8; i++) {
            int j = tid + 256 * i;
            dh[j] = sh[j];
            dl[j] = sl[j];
        }
    }
    __syncthreads();

    // ---- MMA stage 2 ----
    mma_stage(aHi, aLo, wHi, wLo, mhalf, nq, lane, c);

    // ---- epilogue 2: C + b2 (+relu) -> gmem (streaming stores) ----
    #pragma unroll
    for (int mt = 0; mt < 2; mt++)
        #pragma unroll
        for (int nt = 0; nt < 4; nt++) {
            int col = nq * 32 + nt * 8 + lc;
            float2 bb = *(const float2*)&b2[col];
            float v0 = c[mt][nt][0] + bb.x;
            float v1 = c[mt][nt][1] + bb.y;
            float v2 = c[mt][nt][2] + bb.x;
            float v3 = c[mt][nt][3] + bb.y;
            if (relu2) {
                v0 = fmaxf(v0, 0.f); v1 = fmaxf(v1, 0.f);
                v2 = fmaxf(v2, 0.f); v3 = fmaxf(v3, 0.f);
            }
            int r0 = mhalf * 32 + mt * 16 + gid;
            int n0 = nodeBase + r0;
            int n1 = n0 + 8;
            if (n0 < NN) stcs2(&hout[n0 * DD + col], v0, v1);
            if (n1 < NN) stcs2(&hout[n1 * DD + col], v2, v3);
        }
}

// ---------------- mean pool over sorted batch --------------------------------
__device__ __forceinline__ int lbound_batch(const void* b, int val, int is64) {
    int lo = 0, hi = NN;
    if (is64) {
        const long long* p = (const long long*)b;
        long long v = val;
        while (lo < hi) { int mid = (lo + hi) >> 1; if (p[mid] < v) lo = mid + 1; else hi = mid; }
    } else {
        const int* p = (const int*)b;
        while (lo < hi) { int mid = (lo + hi) >> 1; if (p[mid] < val) lo = mid + 1; else hi = mid; }
    }
    return lo;
}

__global__ void pool_kernel(const float* __restrict__ h,
                            const void* __restrict__ batch,
                            const void* __restrict__ ei,
                            float* __restrict__ out) {
    __shared__ int s_is64;
    if (threadIdx.x == 0) s_is64 = detect64(ei);
    __syncthreads();
    int g = blockIdx.x;
    int d = threadIdx.x & 127;
    int sub = threadIdx.x >> 7;
    int start = lbound_batch(batch, g, s_is64);
    int end   = lbound_batch(batch, g + 1, s_is64);
    float acc = 0.f;
    for (int n = start + sub; n < end; n += 4)
        acc += h[n * DD + d];
    __shared__ float red[512];
    red[threadIdx.x] = acc;
    __syncthreads();
    if (sub == 0) {
        float s = (red[d] + red[d + 128]) + (red[d + 256] + red[d + 384]);
        int cnt = end - start;
        out[g * DD + d] = s / (float)(cnt > 0 ? cnt : 1);
    }
}

// ---------------- launch N+1: restore invariants for next call ---------------
__global__ void __launch_bounds__(512) cleanup_kernel() {
    int idx = blockIdx.x * 512 + threadIdx.x;
    if (idx < NN) g_deg[idx] = 0;
    if (idx < NB) g_desc[idx] = 0ULL;
}

// ---------------- launch ------------------------------------------------------
extern "C" void kernel_launch(void* const* d_in, const int* in_sizes, int n_in,
                              void* d_out, int out_size) {
    const float* x = (const float*)d_in[0];
    const void* ei = d_in[1];
    const void* batch = d_in[2];
    const float *W1[3], *b1[3], *W2[3], *b2[3];
    for (int l = 0; l < 3; l++) {
        W1[l] = (const float*)d_in[3 + 4 * l];
        b1[l] = (const float*)d_in[4 + 4 * l];
        W2[l] = (const float*)d_in[5 + 4 * l];
        b2[l] = (const float*)d_in[6 + 4 * l];
    }
    float* out = (float*)d_out;

    cudaFuncSetAttribute(layer_kernel,
                         cudaFuncAttributeMaxDynamicSharedMemorySize, 98304);

    float *tmp, *h;
    cudaGetSymbolAddress((void**)&tmp, g_tmp);
    cudaGetSymbolAddress((void**)&h, g_h);

    // NE == 3125 * 512 exactly; grids below are exact
    pre_kernel<<<6 + NE / 512, 512>>>(ei, W1[0], W2[0], W1[1], W2[1], W1[2], W2[2]); // 0
    scan_kernel<<<NB, 512>>>();                                                       // 1
    fill_kernel<<<NE / 512, 512>>>(ei);                                               // 2

    const int layer_blocks = (NN + 63) / 64;   // 1563
    layer_kernel<<<layer_blocks, 256, 98304>>>(x,   b1[0], b2[0], h,   0, 1);         // 3 (profiled)
    layer_kernel<<<layer_blocks, 256, 98304>>>(h,   b1[1], b2[1], tmp, 2, 1);         // 4
    layer_kernel<<<layer_blocks, 256, 98304>>>(tmp, b1[2], b2[2], h,   4, 0);         // 5

    pool_kernel<<<NG, 512>>>(h, batch, ei, out);                                      // 6
    cleanup_kernel<<<NB, 512>>>();                                                    // 7
}

// round 7
// speedup vs baseline: 2.1940x; 1.0219x over previous
#include <cuda_runtime.h>
#include <cuda_bf16.h>
#include <cstdint>

#define NN 100000
#define NE 1600000
#define DD 128
#define NG 128
#define NB 196              // scan blocks: 196*512 >= NN
#define TLCNT 1563          // (NN+63)/64 tiles of 64 rows

// ---------------- scratch (static device globals; zero-initialized) ---------
__device__ __align__(16) float g_tmp[NN * DD];
__device__ __align__(16) float g_h[NN * DD];
__device__ int g_deg[NN];                 // zero at load; re-zeroed by cleanup
__device__ int g_rowptr[NN + 1];
__device__ int g_cursor[NN];
__device__ int g_esorted[NE];
__device__ unsigned long long g_desc[NB];
// aggregated tiles, bf16 hi/lo planes, pre-swizzled in MMA smem layout:
// tile t occupies bytes [t*16384, (t+1)*16384); within: row*256 + swizzle
__device__ __align__(16) __nv_bfloat16 g_ahi[TLCNT * 8192];
__device__ __align__(16) __nv_bfloat16 g_alo[TLCNT * 8192];
// pre-transposed, pre-swizzled bf16 hi/lo weights {W1_0,W2_0,W1_1,W2_1,W1_2,W2_2}
__device__ __align__(16) __nv_bfloat16 g_whi[6][16384];
__device__ __align__(16) __nv_bfloat16 g_wlo[6][16384];

// ---------------- inline index-width detection ------------------------------
__device__ __forceinline__ int detect64(const void* p) {
    const unsigned* w = (const unsigned*)p;
    unsigned acc = 0;
    #pragma unroll
    for (int i = 0; i < 16; i++) acc |= w[2 * i + 1];
    return acc == 0u;
}

// ---------------- launch 0: weight prep (blocks 0-5) + degree hist ----------
__device__ __forceinline__ uint32_t w_off(int n, int k) {
    return (uint32_t)(n * 128 + (((k >> 3) ^ (n & 7)) << 3) + (k & 7));
}

__global__ void __launch_bounds__(512) pre_kernel(
        const void* __restrict__ ei,
        const float* w0, const float* w1, const float* w2,
        const float* w3, const float* w4, const float* w5) {
    if (blockIdx.x < 6) {
        const float* src[6] = {w0, w1, w2, w3, w4, w5};
        const float* W = src[blockIdx.x];
        for (int i = threadIdx.x; i < 16384; i += 512) {
            int k = i >> 7, n = i & 127;
            float v = W[i];
            __nv_bfloat16 hi = __float2bfloat16(v);
            __nv_bfloat16 lo = __float2bfloat16(v - __bfloat162float(hi));
            uint32_t idx = w_off(n, k);
            g_whi[blockIdx.x][idx] = hi;
            g_wlo[blockIdx.x][idx] = lo;
        }
        return;
    }
    __shared__ int s_is64;
    if (threadIdx.x == 0) s_is64 = detect64(ei);
    __syncthreads();
    int e = (blockIdx.x - 6) * 512 + threadIdx.x;   // grid exact
    int dst = s_is64 ? (int)((const long long*)ei)[(long)NE + e]
                     : ((const int*)ei)[NE + e];
    atomicAdd(&g_deg[dst], 1);
}

// ---------------- launch 1: single-kernel exclusive scan (lookback) ---------
__global__ void __launch_bounds__(512) scan_kernel() {
    int b = blockIdx.x, t = threadIdx.x;
    int idx = b * 512 + t;
    int v = (idx < NN) ? g_deg[idx] : 0;
    int lane = t & 31, w = t >> 5;
    int x = v;
    #pragma unroll
    for (int o = 1; o < 32; o <<= 1) {
        int u = __shfl_up_sync(~0u, x, o);
        if (lane >= o) x += u;
    }
    __shared__ int ws[16], wo[16];
    __shared__ int s_prefix, s_total;
    if (lane == 31) ws[w] = x;
    __syncthreads();
    if (t < 16) {
        int y = ws[t], z = y;
        #pragma unroll
        for (int o = 1; o < 16; o <<= 1) {
            int u = __shfl_up_sync(0xffffu, z, o, 16);
            if (t >= o) z += u;
        }
        wo[t] = z - y;
        if (t == 15) s_total = z;
    }
    __syncthreads();
    int incl = x + wo[w];
    if (t == 0) {
        int total = s_total;
        atomicExch(&g_desc[b], (1ULL << 32) | (unsigned)total);   // AGGREGATE
        long long running = 0;
        for (int i = b - 1; i >= 0;) {
            unsigned long long d;
            do { d = atomicAdd(&g_desc[i], 0ULL); } while ((d >> 32) == 0ULL);
            running += (unsigned)d;
            if ((d >> 32) == 2ULL) break;   // PREFIX
            i--;
        }
        s_prefix = (int)running;
        atomicExch(&g_desc[b], (2ULL << 32) | (unsigned)(running + total));
    }
    __syncthreads();
    int excl = s_prefix + incl - v;
    if (idx < NN) { g_rowptr[idx] = excl; g_cursor[idx] = excl; }
    if (idx == NN - 1) g_rowptr[NN] = s_prefix + incl;
}

// ---------------- launch 2: CSR fill ----------------------------------------
__global__ void __launch_bounds__(512) fill_kernel(const void* __restrict__ ei) {
    __shared__ int s_is64;
    if (threadIdx.x == 0) s_is64 = detect64(ei);
    __syncthreads();
    int e = blockIdx.x * 512 + threadIdx.x;   // grid exact
    int dst, src;
    if (s_is64) {
        dst = (int)((const long long*)ei)[(long)NE + e];
        src = (int)((const long long*)ei)[e];
    } else {
        dst = ((const int*)ei)[NE + e];
        src = ((const int*)ei)[e];
    }
    int pos = atomicAdd(&g_cursor[dst], 1);
    g_esorted[pos] = src;
}

// ---------------- aggregation: warp-per-node, high occupancy ----------------
// Writes bf16 hi/lo planes in swizzled MMA tile layout.
__global__ void __launch_bounds__(256) agg_kernel(const float* __restrict__ hin) {
    int gw = (blockIdx.x * 256 + threadIdx.x) >> 5;   // node index
    if (gw >= NN) return;
    int lane = threadIdx.x & 31;
    const float4* h4 = (const float4*)hin;
    const int* es = g_esorted;

    float4 acc = __ldg(&h4[gw * 32 + lane]);
    int j = g_rowptr[gw], e = g_rowptr[gw + 1];

    int i0, i1, i2, i3, i4, i5, i6, i7;
    bool have = (j + 8 <= e);
    if (have) {
        i0 = __ldg(&es[j]);     i1 = __ldg(&es[j + 1]);
        i2 = __ldg(&es[j + 2]); i3 = __ldg(&es[j + 3]);
        i4 = __ldg(&es[j + 4]); i5 = __ldg(&es[j + 5]);
        i6 = __ldg(&es[j + 6]); i7 = __ldg(&es[j + 7]);
    }
    #pragma unroll 1
    while (have) {
        float4 v0 = __ldg(&h4[i0 * 32 + lane]);
        float4 v1 = __ldg(&h4[i1 * 32 + lane]);
        float4 v2 = __ldg(&h4[i2 * 32 + lane]);
        float4 v3 = __ldg(&h4[i3 * 32 + lane]);
        float4 v4 = __ldg(&h4[i4 * 32 + lane]);
        float4 v5 = __ldg(&h4[i5 * 32 + lane]);
        float4 v6 = __ldg(&h4[i6 * 32 + lane]);
        float4 v7 = __ldg(&h4[i7 * 32 + lane]);
        bool nxt = (j + 16 <= e);
        int x0, x1, x2, x3, x4, x5, x6, x7;
        if (nxt) {
            x0 = __ldg(&es[j + 8]);  x1 = __ldg(&es[j + 9]);
            x2 = __ldg(&es[j + 10]); x3 = __ldg(&es[j + 11]);
            x4 = __ldg(&es[j + 12]); x5 = __ldg(&es[j + 13]);
            x6 = __ldg(&es[j + 14]); x7 = __ldg(&es[j + 15]);
        }
        acc.x += ((v0.x + v1.x) + (v2.x + v3.x)) + ((v4.x + v5.x) + (v6.x + v7.x));
        acc.y += ((v0.y + v1.y) + (v2.y + v3.y)) + ((v4.y + v5.y) + (v6.y + v7.y));
        acc.z += ((v0.z + v1.z) + (v2.z + v3.z)) + ((v4.z + v5.z) + (v6.z + v7.z));
        acc.w += ((v0.w + v1.w) + (v2.w + v3.w)) + ((v4.w + v5.w) + (v6.w + v7.w));
        j += 8;
        if (nxt) { i0 = x0; i1 = x1; i2 = x2; i3 = x3;
                   i4 = x4; i5 = x5; i6 = x6; i7 = x7; }
        have = nxt;
    }
    for (; j < e; j++) {
        int s = __ldg(&es[j]);
        float4 v = __ldg(&h4[s * 32 + lane]);
        acc.x += v.x; acc.y += v.y; acc.z += v.z; acc.w += v.w;
    }

    // bf16 hi/lo split, write swizzled into tile planes (8B per plane per lane)
    __nv_bfloat16 h0 = __float2bfloat16(acc.x);
    __nv_bfloat16 h1 = __float2bfloat16(acc.y);
    __nv_bfloat16 h2 = __float2bfloat16(acc.z);
    __nv_bfloat16 h3 = __float2bfloat16(acc.w);
    __nv_bfloat16 l0 = __float2bfloat16(acc.x - __bfloat162float(h0));
    __nv_bfloat16 l1 = __float2bfloat16(acc.y - __bfloat162float(h1));
    __nv_bfloat16 l2 = __float2bfloat16(acc.z - __bfloat162float(h2));
    __nv_bfloat16 l3 = __float2bfloat16(acc.w - __bfloat162float(h3));

    int tile = gw >> 6, row = gw & 63;
    int col = lane * 4;
    uint32_t off = (uint32_t)(tile * 16384 + row * 256
                              + (((col >> 3) ^ (row & 7)) << 4) + (col & 7) * 2);
    __nv_bfloat162 ph0 = __halves2bfloat162(h0, h1);
    __nv_bfloat162 ph1 = __halves2bfloat162(h2, h3);
    __nv_bfloat162 pl0 = __halves2bfloat162(l0, l1);
    __nv_bfloat162 pl1 = __halves2bfloat162(l2, l3);
    uint2 hw, lw;
    hw.x = reinterpret_cast<uint32_t&>(ph0);
    hw.y = reinterpret_cast<uint32_t&>(ph1);
    lw.x = reinterpret_cast<uint32_t&>(pl0);
    lw.y = reinterpret_cast<uint32_t&>(pl1);
    *reinterpret_cast<uint2*>(reinterpret_cast<char*>(g_ahi) + off) = hw;
    *reinterpret_cast<uint2*>(reinterpret_cast<char*>(g_alo) + off) = lw;
}

// ---------------- warp-MMA helpers ------------------------------------------
__device__ __forceinline__ uint32_t smem_u32(const void* p) {
    uint32_t a;
    asm("{ .reg .u64 t; cvta.to.shared.u64 t, %1; cvt.u32.u64 %0, t; }"
        : "=r"(a) : "l"(p));
    return a;
}
__device__ __forceinline__ void ldsm4(unsigned r[4], uint32_t addr) {
    asm volatile("ldmatrix.sync.aligned.m8n8.x4.shared.b16 {%0,%1,%2,%3}, [%4];"
                 : "=r"(r[0]), "=r"(r[1]), "=r"(r[2]), "=r"(r[3]) : "r"(addr));
}
__device__ __forceinline__ void mma16816(float c[4], const unsigned a[4],
                                         const unsigned b[2]) {
    asm volatile(
        "mma.sync.aligned.m16n8k16.row.col.f32.bf16.bf16.f32 "
        "{%0,%1,%2,%3}, {%4,%5,%6,%7}, {%8,%9}, {%0,%1,%2,%3};"
        : "+f"(c[0]), "+f"(c[1]), "+f"(c[2]), "+f"(c[3])
        : "r"(a[0]), "r"(a[1]), "r"(a[2]), "r"(a[3]), "r"(b[0]), "r"(b[1]));
}

// 64x128 @ 128x128 stage; warp = 32 rows x 32 cols (2 m-tiles x 4 n-tiles)
__device__ __forceinline__ void mma_stage(uint32_t aHi, uint32_t aLo,
                                          uint32_t wHi, uint32_t wLo,
                                          int mhalf, int nq, int lane,
                                          float c[2][4][4]) {
    #pragma unroll
    for (int mt = 0; mt < 2; mt++)
        #pragma unroll
        for (int nt = 0; nt < 4; nt++)
            #pragma unroll
            for (int q = 0; q < 4; q++) c[mt][nt][q] = 0.f;

    int m = lane >> 3, r = lane & 7;
    uint32_t aRow[2], bRow[2];
    #pragma unroll
    for (int mt = 0; mt < 2; mt++)
        aRow[mt] = (uint32_t)(mhalf * 32 + mt * 16 + (m & 1) * 8 + r) * 256;
    #pragma unroll
    for (int bt = 0; bt < 2; bt++)
        bRow[bt] = (uint32_t)(nq * 32 + bt * 16 + (m >> 1) * 8 + r) * 256;
    int aAdd = m >> 1, bAdd = m & 1;

    #pragma unroll
    for (int k = 0; k < 8; k++) {
        unsigned ah[2][4], al[2][4], bh[2][4], bl[2][4];
        uint32_t ac = (uint32_t)(((k * 2 + aAdd) ^ r) << 4);
        uint32_t bc = (uint32_t)(((k * 2 + bAdd) ^ r) << 4);
        #pragma unroll
        for (int mt = 0; mt < 2; mt++) {
            ldsm4(ah[mt], aHi + aRow[mt] + ac);
            ldsm4(al[mt], aLo + aRow[mt] + ac);
        }
        #pragma unroll
        for (int bt = 0; bt < 2; bt++) {
            ldsm4(bh[bt], wHi + bRow[bt] + bc);
            ldsm4(bl[bt], wLo + bRow[bt] + bc);
        }
        #pragma unroll
        for (int mt = 0; mt < 2; mt++)
            #pragma unroll
            for (int nt = 0; nt < 4; nt++) {
                const unsigned* BH = bh[nt >> 1] + (nt & 1) * 2;
                const unsigned* BL = bl[nt >> 1] + (nt & 1) * 2;
                mma16816(c[mt][nt], ah[mt], BH);
                mma16816(c[mt][nt], al[mt], BH);
                mma16816(c[mt][nt], ah[mt], BL);
            }
    }
}

__device__ __forceinline__ void store_hilo(char* pH, char* pL, int row, int col,
                                           float f0, float f1) {
    __nv_bfloat16 h0 = __float2bfloat16(f0), h1 = __float2bfloat16(f1);
    __nv_bfloat16 l0 = __float2bfloat16(f0 - __bfloat162float(h0));
    __nv_bfloat16 l1 = __float2bfloat16(f1 - __bfloat162float(h1));
    uint32_t off = (uint32_t)(row * 256 + (((col >> 3) ^ (row & 7)) << 4)
                              + (col & 7) * 2);
    *(__nv_bfloat162*)(pH + off) = __halves2bfloat162(h0, h1);
    *(__nv_bfloat162*)(pL + off) = __halves2bfloat162(l0, l1);
}

__device__ __forceinline__ void stcs2(float* p, float v0, float v1) {
    asm volatile("st.global.cs.v2.f32 [%0], {%1,%2};" :: "l"(p), "f"(v0), "f"(v1)
                 : "memory");
}

// ---------------- MMA kernel: plane copy -> MMA1 -> relu -> MMA2 ------------
// 256 threads, 64-row tile, 96KB smem -> 2 CTAs/SM; tensor-bound.
__global__ void __launch_bounds__(256, 2) mma_kernel(
        const float* __restrict__ b1, const float* __restrict__ b2,
        float* __restrict__ hout, int widx, int relu2) {
    extern __shared__ char smem[];
    char* pAhi = smem;             // 64 x 256B = 16KB
    char* pAlo = smem + 16384;
    char* pWhi = smem + 32768;     // 128 x 256B = 32KB
    char* pWlo = smem + 65536;

    int tid = threadIdx.x;
    int lane = tid & 31, wid = tid >> 5;
    int nodeBase = blockIdx.x * 64;

    // ---- stage W1 + A planes (all linear copies; layouts pre-swizzled) ----
    {
        const float4* sh = (const float4*)g_whi[widx];
        const float4* sl = (const float4*)g_wlo[widx];
        const float4* aH = (const float4*)(g_ahi + (size_t)blockIdx.x * 8192);
        const float4* aL = (const float4*)(g_alo + (size_t)blockIdx.x * 8192);
        float4* dWh = (float4*)pWhi;
        float4* dWl = (float4*)pWlo;
        float4* dAh = (float4*)pAhi;
        float4* dAl = (float4*)pAlo;
        #pragma unroll
        for (int i = 0; i < 4; i++) {
            int j = tid + 256 * i;
            dAh[j] = aH[j];
            dAl[j] = aL[j];
        }
        #pragma unroll
        for (int i = 0; i < 8; i++) {
            int j = tid + 256 * i;
            dWh[j] = sh[j];
            dWl[j] = sl[j];
        }
    }
    __syncthreads();

    uint32_t aHi = smem_u32(pAhi), aLo = smem_u32(pAlo);
    uint32_t wHi = smem_u32(pWhi), wLo = smem_u32(pWlo);
    int mhalf = wid & 1;
    int nq = wid >> 1;
    int gid = lane >> 2, lc = (lane & 3) * 2;

    float c[2][4][4];
    // ---- MMA stage 1 ----
    mma_stage(aHi, aLo, wHi, wLo, mhalf, nq, lane, c);
    __syncthreads();

    // ---- epilogue 1: relu(C+b1) -> bf16 hi/lo into A tiles ----
    #pragma unroll
    for (int mt = 0; mt < 2; mt++)
        #pragma unroll
        for (int nt = 0; nt < 4; nt++) {
            int col = nq * 32 + nt * 8 + lc;
            float2 bb = *(const float2*)&b1[col];
            int r0 = mhalf * 32 + mt * 16 + gid;
            float f0 = fmaxf(c[mt][nt][0] + bb.x, 0.f);
            float f1 = fmaxf(c[mt][nt][1] + bb.y, 0.f);
            float f2 = fmaxf(c[mt][nt][2] + bb.x, 0.f);
            float f3 = fmaxf(c[mt][nt][3] + bb.y, 0.f);
            store_hilo(pAhi, pAlo, r0,     col, f0, f1);
            store_hilo(pAhi, pAlo, r0 + 8, col, f2, f3);
        }

    // ---- stage W2 into same buffers ----
    {
        const float4* sh = (const float4*)g_whi[widx + 1];
        const float4* sl = (const float4*)g_wlo[widx + 1];
        float4* dh = (float4*)pWhi;
        float4* dl = (float4*)pWlo;
        #pragma unroll
        for (int i = 0; i < 8; i++) {
            int j = tid + 256 * i;
            dh[j] = sh[j];
            dl[j] = sl[j];
        }
    }
    __syncthreads();

    // ---- MMA stage 2 ----
    mma_stage(aHi, aLo, wHi, wLo, mhalf, nq, lane, c);

    // ---- epilogue 2: C + b2 (+relu) -> gmem (streaming stores) ----
    #pragma unroll
    for (int mt = 0; mt < 2; mt++)
        #pragma unroll
        for (int nt = 0; nt < 4; nt++) {
            int col = nq * 32 + nt * 8 + lc;
            float2 bb = *(const float2*)&b2[col];
            float v0 = c[mt][nt][0] + bb.x;
            float v1 = c[mt][nt][1] + bb.y;
            float v2 = c[mt][nt][2] + bb.x;
            float v3 = c[mt][nt][3] + bb.y;
            if (relu2) {
                v0 = fmaxf(v0, 0.f); v1 = fmaxf(v1, 0.f);
                v2 = fmaxf(v2, 0.f); v3 = fmaxf(v3, 0.f);
            }
            int r0 = mhalf * 32 + mt * 16 + gid;
            int n0 = nodeBase + r0;
            int n1 = n0 + 8;
            if (n0 < NN) stcs2(&hout[n0 * DD + col], v0, v1);
            if (n1 < NN) stcs2(&hout[n1 * DD + col], v2, v3);
        }
}

// ---------------- mean pool over sorted batch --------------------------------
__device__ __forceinline__ int lbound_batch(const void* b, int val, int is64) {
    int lo = 0, hi = NN;
    if (is64) {
        const long long* p = (const long long*)b;
        long long v = val;
        while (lo < hi) { int mid = (lo + hi) >> 1; if (p[mid] < v) lo = mid + 1; else hi = mid; }
    } else {
        const int* p = (const int*)b;
        while (lo < hi) { int mid = (lo + hi) >> 1; if (p[mid] < val) lo = mid + 1; else hi = mid; }
    }
    return lo;
}

__global__ void pool_kernel(const float* __restrict__ h,
                            const void* __restrict__ batch,
                            const void* __restrict__ ei,
                            float* __restrict__ out) {
    __shared__ int s_is64;
    if (threadIdx.x == 0) s_is64 = detect64(ei);
    __syncthreads();
    int g = blockIdx.x;
    int d = threadIdx.x & 127;
    int sub = threadIdx.x >> 7;
    int start = lbound_batch(batch, g, s_is64);
    int end   = lbound_batch(batch, g + 1, s_is64);
    float acc = 0.f;
    for (int n = start + sub; n < end; n += 4)
        acc += h[n * DD + d];
    __shared__ float red[512];
    red[threadIdx.x] = acc;
    __syncthreads();
    if (sub == 0) {
        float s = (red[d] + red[d + 128]) + (red[d + 256] + red[d + 384]);
        int cnt = end - start;
        out[g * DD + d] = s / (float)(cnt > 0 ? cnt : 1);
    }
}

// ---------------- restore invariants for next call ---------------------------
__global__ void __launch_bounds__(512) cleanup_kernel() {
    int idx = blockIdx.x * 512 + threadIdx.x;
    if (idx < NN) g_deg[idx] = 0;
    if (idx < NB) g_desc[idx] = 0ULL;
}

// ---------------- launch ------------------------------------------------------
extern "C" void kernel_launch(void* const* d_in, const int* in_sizes, int n_in,
                              void* d_out, int out_size) {
    const float* x = (const float*)d_in[0];
    const void* ei = d_in[1];
    const void* batch = d_in[2];
    const float *W1[3], *b1[3], *W2[3], *b2[3];
    for (int l = 0; l < 3; l++) {
        W1[l] = (const float*)d_in[3 + 4 * l];
        b1[l] = (const float*)d_in[4 + 4 * l];
        W2[l] = (const float*)d_in[5 + 4 * l];
        b2[l] = (const float*)d_in[6 + 4 * l];
    }
    float* out = (float*)d_out;

    cudaFuncSetAttribute(mma_kernel,
                         cudaFuncAttributeMaxDynamicSharedMemorySize, 98304);

    float *tmp, *h;
    cudaGetSymbolAddress((void**)&tmp, g_tmp);
    cudaGetSymbolAddress((void**)&h, g_h);

    const int agg_blocks = (NN * 32 + 255) / 256;   // 12500

    // NE == 3125 * 512 exactly; prologue grids exact
    pre_kernel<<<6 + NE / 512, 512>>>(ei, W1[0], W2[0], W1[1], W2[1], W1[2], W2[2]); // 0
    scan_kernel<<<NB, 512>>>();                                                       // 1
    fill_kernel<<<NE / 512, 512>>>(ei);                                               // 2

    agg_kernel<<<agg_blocks, 256>>>(x);                                               // 3 (profiled)
    mma_kernel<<<TLCNT, 256, 98304>>>(b1[0], b2[0], h,   0, 1);                       // 4
    agg_kernel<<<agg_blocks, 256>>>(h);                                               // 5
    mma_kernel<<<TLCNT, 256, 98304>>>(b1[1], b2[1], tmp, 2, 1);                       // 6
    agg_kernel<<<agg_blocks, 256>>>(tmp);                                             // 7
    mma_kernel<<<TLCNT, 256, 98304>>>(b1[2], b2[2], h,   4, 0);                       // 8

    pool_kernel<<<NG, 512>>>(h, batch, ei, out);                                      // 9
    cleanup_kernel<<<NB, 512>>>();                                                    // 10
}

// round 8
// speedup vs baseline: 2.3377x; 1.0655x over previous
#include <cuda_runtime.h>
#include <cuda_bf16.h>
#include <cuda_fp16.h>
#include <cstdint>

#define NN 100000
#define NE 1600000
#define DD 128
#define NG 128
#define NB 196              // scan blocks: 196*512 >= NN
#define TLCNT 1563          // (NN+63)/64 tiles of 64 rows

// ---------------- scratch (static device globals; zero-initialized) ---------
__device__ __align__(16) float g_h[NN * DD];        // final fp32 activations
__device__ __align__(16) __half g_hh0[NN * DD];     // fp16 activations (layer0 out)
__device__ __align__(16) __half g_hh1[NN * DD];     // fp16 activations (layer1 out)
__device__ int g_deg[NN];
__device__ int g_rowptr[NN + 1];
__device__ int g_cursor[NN];
__device__ int g_esorted[NE];
__device__ unsigned long long g_desc[NB];
// aggregated tiles, bf16 hi/lo planes, pre-swizzled in MMA smem layout
__device__ __align__(16) __nv_bfloat16 g_ahi[TLCNT * 8192];
__device__ __align__(16) __nv_bfloat16 g_alo[TLCNT * 8192];
// pre-transposed, pre-swizzled bf16 hi/lo weights {W1_0,W2_0,W1_1,W2_1,W1_2,W2_2}
__device__ __align__(16) __nv_bfloat16 g_whi[6][16384];
__device__ __align__(16) __nv_bfloat16 g_wlo[6][16384];

// ---------------- inline index-width detection ------------------------------
__device__ __forceinline__ int detect64(const void* p) {
    const unsigned* w = (const unsigned*)p;
    unsigned acc = 0;
    #pragma unroll
    for (int i = 0; i < 16; i++) acc |= w[2 * i + 1];
    return acc == 0u;
}

// ---------------- launch 0: weight prep (blocks 0-5) + degree hist ----------
__device__ __forceinline__ uint32_t w_off(int n, int k) {
    return (uint32_t)(n * 128 + (((k >> 3) ^ (n & 7)) << 3) + (k & 7));
}

__global__ void __launch_bounds__(512) pre_kernel(
        const void* __restrict__ ei,
        const float* w0, const float* w1, const float* w2,
        const float* w3, const float* w4, const float* w5) {
    if (blockIdx.x < 6) {
        const float* src[6] = {w0, w1, w2, w3, w4, w5};
        const float* W = src[blockIdx.x];
        for (int i = threadIdx.x; i < 16384; i += 512) {
            int k = i >> 7, n = i & 127;
            float v = W[i];
            __nv_bfloat16 hi = __float2bfloat16(v);
            __nv_bfloat16 lo = __float2bfloat16(v - __bfloat162float(hi));
            uint32_t idx = w_off(n, k);
            g_whi[blockIdx.x][idx] = hi;
            g_wlo[blockIdx.x][idx] = lo;
        }
        return;
    }
    __shared__ int s_is64;
    if (threadIdx.x == 0) s_is64 = detect64(ei);
    __syncthreads();
    int e = (blockIdx.x - 6) * 512 + threadIdx.x;   // grid exact
    int dst = s_is64 ? (int)((const long long*)ei)[(long)NE + e]
                     : ((const int*)ei)[NE + e];
    atomicAdd(&g_deg[dst], 1);
}

// ---------------- launch 1: single-kernel exclusive scan (lookback) ---------
__global__ void __launch_bounds__(512) scan_kernel() {
    int b = blockIdx.x, t = threadIdx.x;
    int idx = b * 512 + t;
    int v = (idx < NN) ? g_deg[idx] : 0;
    int lane = t & 31, w = t >> 5;
    int x = v;
    #pragma unroll
    for (int o = 1; o < 32; o <<= 1) {
        int u = __shfl_up_sync(~0u, x, o);
        if (lane >= o) x += u;
    }
    __shared__ int ws[16], wo[16];
    __shared__ int s_prefix, s_total;
    if (lane == 31) ws[w] = x;
    __syncthreads();
    if (t < 16) {
        int y = ws[t], z = y;
        #pragma unroll
        for (int o = 1; o < 16; o <<= 1) {
            int u = __shfl_up_sync(0xffffu, z, o, 16);
            if (t >= o) z += u;
        }
        wo[t] = z - y;
        if (t == 15) s_total = z;
    }
    __syncthreads();
    int incl = x + wo[w];
    if (t == 0) {
        int total = s_total;
        atomicExch(&g_desc[b], (1ULL << 32) | (unsigned)total);   // AGGREGATE
        long long running = 0;
        for (int i = b - 1; i >= 0;) {
            unsigned long long d;
            do { d = atomicAdd(&g_desc[i], 0ULL); } while ((d >> 32) == 0ULL);
            running += (unsigned)d;
            if ((d >> 32) == 2ULL) break;   // PREFIX
            i--;
        }
        s_prefix = (int)running;
        atomicExch(&g_desc[b], (2ULL << 32) | (unsigned)(running + total));
    }
    __syncthreads();
    int excl = s_prefix + incl - v;
    if (idx < NN) { g_rowptr[idx] = excl; g_cursor[idx] = excl; }
    if (idx == NN - 1) g_rowptr[NN] = s_prefix + incl;
}

// ---------------- launch 2: CSR fill ----------------------------------------
__global__ void __launch_bounds__(512) fill_kernel(const void* __restrict__ ei) {
    __shared__ int s_is64;
    if (threadIdx.x == 0) s_is64 = detect64(ei);
    __syncthreads();
    int e = blockIdx.x * 512 + threadIdx.x;   // grid exact
    int dst, src;
    if (s_is64) {
        dst = (int)((const long long*)ei)[(long)NE + e];
        src = (int)((const long long*)ei)[e];
    } else {
        dst = ((const int*)ei)[NE + e];
        src = ((const int*)ei)[e];
    }
    int pos = atomicAdd(&g_cursor[dst], 1);
    g_esorted[pos] = src;
}

// ---------------- aggregation: warp-per-node, L2-roofline-bound -------------
// FP16IN=0: rows are fp32 (512B); FP16IN=1: rows are fp16 (256B).
template <int FP16IN>
__global__ void __launch_bounds__(256) agg_kernel(const void* __restrict__ hin) {
    int gw = (blockIdx.x * 256 + threadIdx.x) >> 5;   // node index
    if (gw >= NN) return;
    int lane = threadIdx.x & 31;
    const float4* h4 = (const float4*)hin;
    const uint2* h2 = (const uint2*)hin;
    const int* es = g_esorted;

    float4 acc;
    if (FP16IN) {
        uint2 u = __ldg(&h2[gw * 32 + lane]);
        float2 a = __half22float2(*reinterpret_cast<__half2*>(&u.x));
        float2 b = __half22float2(*reinterpret_cast<__half2*>(&u.y));
        acc = make_float4(a.x, a.y, b.x, b.y);
    } else {
        acc = __ldg(&h4[gw * 32 + lane]);
    }
    int j = g_rowptr[gw], e = g_rowptr[gw + 1];

    int i0, i1, i2, i3, i4, i5, i6, i7;
    bool have = (j + 8 <= e);
    if (have) {
        i0 = __ldg(&es[j]);     i1 = __ldg(&es[j + 1]);
        i2 = __ldg(&es[j + 2]); i3 = __ldg(&es[j + 3]);
        i4 = __ldg(&es[j + 4]); i5 = __ldg(&es[j + 5]);
        i6 = __ldg(&es[j + 6]); i7 = __ldg(&es[j + 7]);
    }
    #pragma unroll 1
    while (have) {
        float4 v[8];
        if (FP16IN) {
            uint2 u0 = __ldg(&h2[i0 * 32 + lane]);
            uint2 u1 = __ldg(&h2[i1 * 32 + lane]);
            uint2 u2 = __ldg(&h2[i2 * 32 + lane]);
            uint2 u3 = __ldg(&h2[i3 * 32 + lane]);
            uint2 u4 = __ldg(&h2[i4 * 32 + lane]);
            uint2 u5 = __ldg(&h2[i5 * 32 + lane]);
            uint2 u6 = __ldg(&h2[i6 * 32 + lane]);
            uint2 u7 = __ldg(&h2[i7 * 32 + lane]);
            uint2 uu[8] = {u0, u1, u2, u3, u4, u5, u6, u7};
            #pragma unroll
            for (int q = 0; q < 8; q++) {
                float2 a = __half22float2(*reinterpret_cast<__half2*>(&uu[q].x));
                float2 b = __half22float2(*reinterpret_cast<__half2*>(&uu[q].y));
                v[q] = make_float4(a.x, a.y, b.x, b.y);
            }
        } else {
            v[0] = __ldg(&h4[i0 * 32 + lane]);
            v[1] = __ldg(&h4[i1 * 32 + lane]);
            v[2] = __ldg(&h4[i2 * 32 + lane]);
            v[3] = __ldg(&h4[i3 * 32 + lane]);
            v[4] = __ldg(&h4[i4 * 32 + lane]);
            v[5] = __ldg(&h4[i5 * 32 + lane]);
            v[6] = __ldg(&h4[i6 * 32 + lane]);
            v[7] = __ldg(&h4[i7 * 32 + lane]);
        }
        bool nxt = (j + 16 <= e);
        int x0, x1, x2, x3, x4, x5, x6, x7;
        if (nxt) {
            x0 = __ldg(&es[j + 8]);  x1 = __ldg(&es[j + 9]);
            x2 = __ldg(&es[j + 10]); x3 = __ldg(&es[j + 11]);
            x4 = __ldg(&es[j + 12]); x5 = __ldg(&es[j + 13]);
            x6 = __ldg(&es[j + 14]); x7 = __ldg(&es[j + 15]);
        }
        acc.x += ((v[0].x + v[1].x) + (v[2].x + v[3].x)) + ((v[4].x + v[5].x) + (v[6].x + v[7].x));
        acc.y += ((v[0].y + v[1].y) + (v[2].y + v[3].y)) + ((v[4].y + v[5].y) + (v[6].y + v[7].y));
        acc.z += ((v[0].z + v[1].z) + (v[2].z + v[3].z)) + ((v[4].z + v[5].z) + (v[6].z + v[7].z));
        acc.w += ((v[0].w + v[1].w) + (v[2].w + v[3].w)) + ((v[4].w + v[5].w) + (v[6].w + v[7].w));
        j += 8;
        if (nxt) { i0 = x0; i1 = x1; i2 = x2; i3 = x3;
                   i4 = x4; i5 = x5; i6 = x6; i7 = x7; }
        have = nxt;
    }
    for (; j < e; j++) {
        int s = __ldg(&es[j]);
        if (FP16IN) {
            uint2 u = __ldg(&h2[s * 32 + lane]);
            float2 a = __half22float2(*reinterpret_cast<__half2*>(&u.x));
            float2 b = __half22float2(*reinterpret_cast<__half2*>(&u.y));
            acc.x += a.x; acc.y += a.y; acc.z += b.x; acc.w += b.y;
        } else {
            float4 v = __ldg(&h4[s * 32 + lane]);
            acc.x += v.x; acc.y += v.y; acc.z += v.z; acc.w += v.w;
        }
    }

    // bf16 hi/lo split, write swizzled into tile planes
    __nv_bfloat16 h0 = __float2bfloat16(acc.x);
    __nv_bfloat16 h1 = __float2bfloat16(acc.y);
    __nv_bfloat16 h2v = __float2bfloat16(acc.z);
    __nv_bfloat16 h3 = __float2bfloat16(acc.w);
    __nv_bfloat16 l0 = __float2bfloat16(acc.x - __bfloat162float(h0));
    __nv_bfloat16 l1 = __float2bfloat16(acc.y - __bfloat162float(h1));
    __nv_bfloat16 l2 = __float2bfloat16(acc.z - __bfloat162float(h2v));
    __nv_bfloat16 l3 = __float2bfloat16(acc.w - __bfloat162float(h3));

    int tile = gw >> 6, row = gw & 63;
    int col = lane * 4;
    uint32_t off = (uint32_t)(tile * 16384 + row * 256
                              + (((col >> 3) ^ (row & 7)) << 4) + (col & 7) * 2);
    __nv_bfloat162 ph0 = __halves2bfloat162(h0, h1);
    __nv_bfloat162 ph1 = __halves2bfloat162(h2v, h3);
    __nv_bfloat162 pl0 = __halves2bfloat162(l0, l1);
    __nv_bfloat162 pl1 = __halves2bfloat162(l2, l3);
    uint2 hw, lw;
    hw.x = reinterpret_cast<uint32_t&>(ph0);
    hw.y = reinterpret_cast<uint32_t&>(ph1);
    lw.x = reinterpret_cast<uint32_t&>(pl0);
    lw.y = reinterpret_cast<uint32_t&>(pl1);
    *reinterpret_cast<uint2*>(reinterpret_cast<char*>(g_ahi) + off) = hw;
    *reinterpret_cast<uint2*>(reinterpret_cast<char*>(g_alo) + off) = lw;
}

// ---------------- warp-MMA helpers ------------------------------------------
__device__ __forceinline__ uint32_t smem_u32(const void* p) {
    uint32_t a;
    asm("{ .reg .u64 t; cvta.to.shared.u64 t, %1; cvt.u32.u64 %0, t; }"
        : "=r"(a) : "l"(p));
    return a;
}
__device__ __forceinline__ void ldsm4(unsigned r[4], uint32_t addr) {
    asm volatile("ldmatrix.sync.aligned.m8n8.x4.shared.b16 {%0,%1,%2,%3}, [%4];"
                 : "=r"(r[0]), "=r"(r[1]), "=r"(r[2]), "=r"(r[3]) : "r"(addr));
}
__device__ __forceinline__ void mma16816(float c[4], const unsigned a[4],
                                         const unsigned b[2]) {
    asm volatile(
        "mma.sync.aligned.m16n8k16.row.col.f32.bf16.bf16.f32 "
        "{%0,%1,%2,%3}, {%4,%5,%6,%7}, {%8,%9}, {%0,%1,%2,%3};"
        : "+f"(c[0]), "+f"(c[1]), "+f"(c[2]), "+f"(c[3])
        : "r"(a[0]), "r"(a[1]), "r"(a[2]), "r"(a[3]), "r"(b[0]), "r"(b[1]));
}

// 64x128 @ 128x128 stage; warp = 32 rows x 32 cols (2 m-tiles x 4 n-tiles)
__device__ __forceinline__ void mma_stage(uint32_t aHi, uint32_t aLo,
                                          uint32_t wHi, uint32_t wLo,
                                          int mhalf, int nq, int lane,
                                          float c[2][4][4]) {
    #pragma unroll
    for (int mt = 0; mt < 2; mt++)
        #pragma unroll
        for (int nt = 0; nt < 4; nt++)
            #pragma unroll
            for (int q = 0; q < 4; q++) c[mt][nt][q] = 0.f;

    int m = lane >> 3, r = lane & 7;
    uint32_t aRow[2], bRow[2];
    #pragma unroll
    for (int mt = 0; mt < 2; mt++)
        aRow[mt] = (uint32_t)(mhalf * 32 + mt * 16 + (m & 1) * 8 + r) * 256;
    #pragma unroll
    for (int bt = 0; bt < 2; bt++)
        bRow[bt] = (uint32_t)(nq * 32 + bt * 16 + (m >> 1) * 8 + r) * 256;
    int aAdd = m >> 1, bAdd = m & 1;

    #pragma unroll
    for (int k = 0; k < 8; k++) {
        unsigned ah[2][4], al[2][4], bh[2][4], bl[2][4];
        uint32_t ac = (uint32_t)(((k * 2 + aAdd) ^ r) << 4);
        uint32_t bc = (uint32_t)(((k * 2 + bAdd) ^ r) << 4);
        #pragma unroll
        for (int mt = 0; mt < 2; mt++) {
            ldsm4(ah[mt], aHi + aRow[mt] + ac);
            ldsm4(al[mt], aLo + aRow[mt] + ac);
        }
        #pragma unroll
        for (int bt = 0; bt < 2; bt++) {
            ldsm4(bh[bt], wHi + bRow[bt] + bc);
            ldsm4(bl[bt], wLo + bRow[bt] + bc);
        }
        #pragma unroll
        for (int mt = 0; mt < 2; mt++)
            #pragma unroll
            for (int nt = 0; nt < 4; nt++) {
                const unsigned* BH = bh[nt >> 1] + (nt & 1) * 2;
                const unsigned* BL = bl[nt >> 1] + (nt & 1) * 2;
                mma16816(c[mt][nt], ah[mt], BH);
                mma16816(c[mt][nt], al[mt], BH);
                mma16816(c[mt][nt], ah[mt], BL);
            }
    }
}

__device__ __forceinline__ void store_hilo(char* pH, char* pL, int row, int col,
                                           float f0, float f1) {
    __nv_bfloat16 h0 = __float2bfloat16(f0), h1 = __float2bfloat16(f1);
    __nv_bfloat16 l0 = __float2bfloat16(f0 - __bfloat162float(h0));
    __nv_bfloat16 l1 = __float2bfloat16(f1 - __bfloat162float(h1));
    uint32_t off = (uint32_t)(row * 256 + (((col >> 3) ^ (row & 7)) << 4)
                              + (col & 7) * 2);
    *(__nv_bfloat162*)(pH + off) = __halves2bfloat162(h0, h1);
    *(__nv_bfloat162*)(pL + off) = __halves2bfloat162(l0, l1);
}

__device__ __forceinline__ void stcs2(float* p, float v0, float v1) {
    asm volatile("st.global.cs.v2.f32 [%0], {%1,%2};" :: "l"(p), "f"(v0), "f"(v1)
                 : "memory");
}
__device__ __forceinline__ void stcsh2(__half* p, float v0, float v1) {
    __half2 h = __floats2half2_rn(v0, v1);
    unsigned u = reinterpret_cast<unsigned&>(h);
    asm volatile("st.global.cs.u32 [%0], %1;" :: "l"(p), "r"(u) : "memory");
}

// ---------------- MMA kernel: plane copy -> MMA1 -> relu -> MMA2 ------------
__global__ void __launch_bounds__(256, 2) mma_kernel(
        const float* __restrict__ b1, const float* __restrict__ b2,
        float* __restrict__ hout32, __half* __restrict__ hout16,
        int widx, int relu2) {
    extern __shared__ char smem[];
    char* pAhi = smem;             // 64 x 256B = 16KB
    char* pAlo = smem + 16384;
    char* pWhi = smem + 32768;     // 128 x 256B = 32KB
    char* pWlo = smem + 65536;

    int tid = threadIdx.x;
    int lane = tid & 31, wid = tid >> 5;
    int nodeBase = blockIdx.x * 64;

    // ---- stage W1 + A planes (linear copies; layouts pre-swizzled) ----
    {
        const float4* sh = (const float4*)g_whi[widx];
        const float4* sl = (const float4*)g_wlo[widx];
        const float4* aH = (const float4*)(g_ahi + (size_t)blockIdx.x * 8192);
        const float4* aL = (const float4*)(g_alo + (size_t)blockIdx.x * 8192);
        float4* dWh = (float4*)pWhi;
        float4* dWl = (float4*)pWlo;
        float4* dAh = (float4*)pAhi;
        float4* dAl = (float4*)pAlo;
        #pragma unroll
        for (int i = 0; i < 4; i++) {
            int j = tid + 256 * i;
            dAh[j] = aH[j];
            dAl[j] = aL[j];
        }
        #pragma unroll
        for (int i = 0; i < 8; i++) {
            int j = tid + 256 * i;
            dWh[j] = sh[j];
            dWl[j] = sl[j];
        }
    }
    __syncthreads();

    uint32_t aHi = smem_u32(pAhi), aLo = smem_u32(pAlo);
    uint32_t wHi = smem_u32(pWhi), wLo = smem_u32(pWlo);
    int mhalf = wid & 1;
    int nq = wid >> 1;
    int gid = lane >> 2, lc = (lane & 3) * 2;

    float c[2][4][4];
    mma_stage(aHi, aLo, wHi, wLo, mhalf, nq, lane, c);
    __syncthreads();

    // ---- epilogue 1: relu(C+b1) -> bf16 hi/lo into A tiles ----
    #pragma unroll
    for (int mt = 0; mt < 2; mt++)
        #pragma unroll
        for (int nt = 0; nt < 4; nt++) {
            int col = nq * 32 + nt * 8 + lc;
            float2 bb = *(const float2*)&b1[col];
            int r0 = mhalf * 32 + mt * 16 + gid;
            float f0 = fmaxf(c[mt][nt][0] + bb.x, 0.f);
            float f1 = fmaxf(c[mt][nt][1] + bb.y, 0.f);
            float f2 = fmaxf(c[mt][nt][2] + bb.x, 0.f);
            float f3 = fmaxf(c[mt][nt][3] + bb.y, 0.f);
            store_hilo(pAhi, pAlo, r0,     col, f0, f1);
            store_hilo(pAhi, pAlo, r0 + 8, col, f2, f3);
        }

    // ---- stage W2 ----
    {
        const float4* sh = (const float4*)g_whi[widx + 1];
        const float4* sl = (const float4*)g_wlo[widx + 1];
        float4* dh = (float4*)pWhi;
        float4* dl = (float4*)pWlo;
        #pragma unroll
        for (int i = 0; i < 8; i++) {
            int j = tid + 256 * i;
            dh[j] = sh[j];
            dl[j] = sl[j];
        }
    }
    __syncthreads();

    mma_stage(aHi, aLo, wHi, wLo, mhalf, nq, lane, c);

    // ---- epilogue 2: C + b2 (+relu) -> gmem ----
    #pragma unroll
    for (int mt = 0; mt < 2; mt++)
        #pragma unroll
        for (int nt = 0; nt < 4; nt++) {
            int col = nq * 32 + nt * 8 + lc;
            float2 bb = *(const float2*)&b2[col];
            float v0 = c[mt][nt][0] + bb.x;
            float v1 = c[mt][nt][1] + bb.y;
            float v2 = c[mt][nt][2] + bb.x;
            float v3 = c[mt][nt][3] + bb.y;
            if (relu2) {
                v0 = fmaxf(v0, 0.f); v1 = fmaxf(v1, 0.f);
                v2 = fmaxf(v2, 0.f); v3 = fmaxf(v3, 0.f);
            }
            int r0 = mhalf * 32 + mt * 16 + gid;
            int n0 = nodeBase + r0;
            int n1 = n0 + 8;
            if (relu2) {   // intermediate layers: fp16 activations
                if (n0 < NN) stcsh2(&hout16[n0 * DD + col], v0, v1);
                if (n1 < NN) stcsh2(&hout16[n1 * DD + col], v2, v3);
            } else {       // last layer: fp32 for pooling
                if (n0 < NN) stcs2(&hout32[n0 * DD + col], v0, v1);
                if (n1 < NN) stcs2(&hout32[n1 * DD + col], v2, v3);
            }
        }
}

// ---------------- mean pool over sorted batch --------------------------------
__device__ __forceinline__ int lbound_batch(const void* b, int val, int is64) {
    int lo = 0, hi = NN;
    if (is64) {
        const long long* p = (const long long*)b;
        long long v = val;
        while (lo < hi) { int mid = (lo + hi) >> 1; if (p[mid] < v) lo = mid + 1; else hi = mid; }
    } else {
        const int* p = (const int*)b;
        while (lo < hi) { int mid = (lo + hi) >> 1; if (p[mid] < val) lo = mid + 1; else hi = mid; }
    }
    return lo;
}

__global__ void pool_kernel(const float* __restrict__ h,
                            const void* __restrict__ batch,
                            const void* __restrict__ ei,
                            float* __restrict__ out) {
    __shared__ int s_is64;
    if (threadIdx.x == 0) s_is64 = detect64(ei);
    __syncthreads();
    int g = blockIdx.x;
    int d = threadIdx.x & 127;
    int sub = threadIdx.x >> 7;
    int start = lbound_batch(batch, g, s_is64);
    int end   = lbound_batch(batch, g + 1, s_is64);
    float acc = 0.f;
    for (int n = start + sub; n < end; n += 4)
        acc += h[n * DD + d];
    __shared__ float red[512];
    red[threadIdx.x] = acc;
    __syncthreads();
    if (sub == 0) {
        float s = (red[d] + red[d + 128]) + (red[d + 256] + red[d + 384]);
        int cnt = end - start;
        out[g * DD + d] = s / (float)(cnt > 0 ? cnt : 1);
    }
}

// ---------------- restore invariants for next call ---------------------------
__global__ void __launch_bounds__(512) cleanup_kernel() {
    int idx = blockIdx.x * 512 + threadIdx.x;
    if (idx < NN) g_deg[idx] = 0;
    if (idx < NB) g_desc[idx] = 0ULL;
}

// ---------------- launch ------------------------------------------------------
extern "C" void kernel_launch(void* const* d_in, const int* in_sizes, int n_in,
                              void* d_out, int out_size) {
    const float* x = (const float*)d_in[0];
    const void* ei = d_in[1];
    const void* batch = d_in[2];
    const float *W1[3], *b1[3], *W2[3], *b2[3];
    for (int l = 0; l < 3; l++) {
        W1[l] = (const float*)d_in[3 + 4 * l];
        b1[l] = (const float*)d_in[4 + 4 * l];
        W2[l] = (const float*)d_in[5 + 4 * l];
        b2[l] = (const float*)d_in[6 + 4 * l];
    }
    float* out = (float*)d_out;

    cudaFuncSetAttribute(mma_kernel,
                         cudaFuncAttributeMaxDynamicSharedMemorySize, 98304);

    float* h;
    __half *hh0, *hh1;
    cudaGetSymbolAddress((void**)&h, g_h);
    cudaGetSymbolAddress((void**)&hh0, g_hh0);
    cudaGetSymbolAddress((void**)&hh1, g_hh1);

    const int agg_blocks = (NN * 32 + 255) / 256;   // 12500

    pre_kernel<<<6 + NE / 512, 512>>>(ei, W1[0], W2[0], W1[1], W2[1], W1[2], W2[2]); // 0
    scan_kernel<<<NB, 512>>>();                                                       // 1
    fill_kernel<<<NE / 512, 512>>>(ei);                                               // 2

    agg_kernel<0><<<agg_blocks, 256>>>(x);                                            // 3
    mma_kernel<<<TLCNT, 256, 98304>>>(b1[0], b2[0], nullptr, hh0, 0, 1);              // 4
    agg_kernel<1><<<agg_blocks, 256>>>(hh0);                                          // 5
    mma_kernel<<<TLCNT, 256, 98304>>>(b1[1], b2[1], nullptr, hh1, 2, 1);              // 6
    agg_kernel<1><<<agg_blocks, 256>>>(hh1);                                          // 7
    mma_kernel<<<TLCNT, 256, 98304>>>(b1[2], b2[2], h, nullptr, 4, 0);                // 8

    pool_kernel<<<NG, 512>>>(h, batch, ei, out);                                      // 9
    cleanup_kernel<<<NB, 512>>>();                                                    // 10
}

// round 9
// speedup vs baseline: 2.5953x; 1.1102x over previous
#include <cuda_runtime.h>
#include <cuda_bf16.h>
#include <cuda_fp16.h>
#include <cstdint>

#define NN 100000
#define NE 1600000
#define DD 128
#define NG 128
#define NB 196              // scan blocks: 196*512 >= NN
#define TLCNT 1563          // (NN+63)/64 tiles of 64 rows
#define HISTB 3125          // NE/512
#define XCONVB 3125         // NN*DD/4096

// ---------------- scratch (static device globals; zero-initialized) ---------
__device__ __align__(16) float g_h[NN * DD];        // final fp32 activations
__device__ __align__(16) __half g_xh[NN * DD];      // fp16 copy of input x
__device__ __align__(16) __half g_hh0[NN * DD];     // fp16 activations (layer0 out)
__device__ __align__(16) __half g_hh1[NN * DD];     // fp16 activations (layer1 out)
__device__ int g_deg[NN];
__device__ int g_rowptr[NN + 1];
__device__ int g_cursor[NN];
__device__ int g_esorted[NE];
__device__ unsigned long long g_desc[NB];
// aggregated tiles, bf16 hi/lo planes, pre-swizzled in MMA smem layout
__device__ __align__(16) __nv_bfloat16 g_ahi[TLCNT * 8192];
__device__ __align__(16) __nv_bfloat16 g_alo[TLCNT * 8192];
// pre-transposed, pre-swizzled bf16 hi/lo weights {W1_0,W2_0,W1_1,W2_1,W1_2,W2_2}
__device__ __align__(16) __nv_bfloat16 g_whi[6][16384];
__device__ __align__(16) __nv_bfloat16 g_wlo[6][16384];

// ---------------- inline index-width detection ------------------------------
__device__ __forceinline__ int detect64(const void* p) {
    const unsigned* w = (const unsigned*)p;
    unsigned acc = 0;
    #pragma unroll
    for (int i = 0; i < 16; i++) acc |= w[2 * i + 1];
    return acc == 0u;
}

// ---------------- launch 0: weight prep + degree hist + x->fp16 -------------
__device__ __forceinline__ uint32_t w_off(int n, int k) {
    return (uint32_t)(n * 128 + (((k >> 3) ^ (n & 7)) << 3) + (k & 7));
}

__global__ void __launch_bounds__(512) pre_kernel(
        const void* __restrict__ ei, const float* __restrict__ x,
        const float* w0, const float* w1, const float* w2,
        const float* w3, const float* w4, const float* w5) {
    if (blockIdx.x < 6) {
        const float* src[6] = {w0, w1, w2, w3, w4, w5};
        const float* W = src[blockIdx.x];
        for (int i = threadIdx.x; i < 16384; i += 512) {
            int k = i >> 7, n = i & 127;
            float v = W[i];
            __nv_bfloat16 hi = __float2bfloat16(v);
            __nv_bfloat16 lo = __float2bfloat16(v - __bfloat162float(hi));
            uint32_t idx = w_off(n, k);
            g_whi[blockIdx.x][idx] = hi;
            g_wlo[blockIdx.x][idx] = lo;
        }
        return;
    }
    if (blockIdx.x >= 6 + HISTB) {
        // x -> fp16 conversion: thread handles 8 consecutive floats
        int base = (blockIdx.x - 6 - HISTB) * 4096 + threadIdx.x * 8;
        float4 a = __ldg((const float4*)(x + base));
        float4 b = __ldg((const float4*)(x + base + 4));
        __half2 p0 = __floats2half2_rn(a.x, a.y);
        __half2 p1 = __floats2half2_rn(a.z, a.w);
        __half2 p2 = __floats2half2_rn(b.x, b.y);
        __half2 p3 = __floats2half2_rn(b.z, b.w);
        uint4 u;
        u.x = reinterpret_cast<uint32_t&>(p0);
        u.y = reinterpret_cast<uint32_t&>(p1);
        u.z = reinterpret_cast<uint32_t&>(p2);
        u.w = reinterpret_cast<uint32_t&>(p3);
        *reinterpret_cast<uint4*>(g_xh + base) = u;
        return;
    }
    __shared__ int s_is64;
    if (threadIdx.x == 0) s_is64 = detect64(ei);
    __syncthreads();
    int e = (blockIdx.x - 6) * 512 + threadIdx.x;   // grid exact
    int dst = s_is64 ? (int)((const long long*)ei)[(long)NE + e]
                     : ((const int*)ei)[NE + e];
    atomicAdd(&g_deg[dst], 1);
}

// ---------------- launch 1: single-kernel exclusive scan ---------------------
// decoupled lookback, warp-parallel (32 predecessors per poll round)
__global__ void __launch_bounds__(512) scan_kernel() {
    int b = blockIdx.x, t = threadIdx.x;
    int idx = b * 512 + t;
    int v = (idx < NN) ? g_deg[idx] : 0;
    int lane = t & 31, w = t >> 5;
    int x = v;
    #pragma unroll
    for (int o = 1; o < 32; o <<= 1) {
        int u = __shfl_up_sync(~0u, x, o);
        if (lane >= o) x += u;
    }
    __shared__ int ws[16], wo[16];
    __shared__ int s_prefix, s_total;
    if (lane == 31) ws[w] = x;
    __syncthreads();
    if (t < 16) {
        int y = ws[t], z = y;
        #pragma unroll
        for (int o = 1; o < 16; o <<= 1) {
            int u = __shfl_up_sync(0xffffu, z, o, 16);
            if (t >= o) z += u;
        }
        wo[t] = z - y;
        if (t == 15) s_total = z;
    }
    __syncthreads();
    int incl = x + wo[w];
    if (t == 0)
        atomicExch(&g_desc[b], (1ULL << 32) | (unsigned)s_total);   // AGGREGATE
    if (t < 32) {
        long long running = 0;
        int i = b - 1 - t;   // lane 0 = nearest predecessor
        while (true) {
            unsigned long long d = (2ULL << 32);   // virtual PREFIX 0 below block 0
            if (i >= 0) {
                do { d = atomicAdd(&g_desc[i], 0ULL); } while ((d >> 32) == 0ULL);
            }
            int isPre = ((d >> 32) == 2ULL);
            unsigned pm = __ballot_sync(~0u, isPre);
            if (pm) {
                int fp = __ffs(pm) - 1;   // closest PREFIX lane
                long long val = (t <= fp) ? (long long)(unsigned)d : 0;
                #pragma unroll
                for (int o = 16; o; o >>= 1) val += __shfl_down_sync(~0u, val, o);
                running += __shfl_sync(~0u, val, 0);
                break;
            } else {
                long long val = (long long)(unsigned)d;
                #pragma unroll
                for (int o = 16; o; o >>= 1) val += __shfl_down_sync(~0u, val, o);
                running += __shfl_sync(~0u, val, 0);
                i -= 32;
            }
        }
        if (t == 0) {
            s_prefix = (int)running;
            atomicExch(&g_desc[b],
                       (2ULL << 32) | (unsigned)(running + s_total));   // PREFIX
        }
    }
    __syncthreads();
    int excl = s_prefix + incl - v;
    if (idx < NN) { g_rowptr[idx] = excl; g_cursor[idx] = excl; }
    if (idx == NN - 1) g_rowptr[NN] = s_prefix + incl;
}

// ---------------- launch 2: CSR fill ----------------------------------------
__global__ void __launch_bounds__(512) fill_kernel(const void* __restrict__ ei) {
    __shared__ int s_is64;
    if (threadIdx.x == 0) s_is64 = detect64(ei);
    __syncthreads();
    int e = blockIdx.x * 512 + threadIdx.x;   // grid exact
    int dst, src;
    if (s_is64) {
        dst = (int)((const long long*)ei)[(long)NE + e];
        src = (int)((const long long*)ei)[e];
    } else {
        dst = ((const int*)ei)[NE + e];
        src = ((const int*)ei)[e];
    }
    int pos = atomicAdd(&g_cursor[dst], 1);
    g_esorted[pos] = src;
}

// ---------------- aggregation: warp-per-node, L2-roofline-bound (fp16 in) ---
__global__ void __launch_bounds__(256) agg_kernel(const __half* __restrict__ hin) {
    int gw = (blockIdx.x * 256 + threadIdx.x) >> 5;   // node index
    if (gw >= NN) return;
    int lane = threadIdx.x & 31;
    const uint2* h2 = (const uint2*)hin;
    const int* es = g_esorted;

    float4 acc;
    {
        uint2 u = __ldg(&h2[gw * 32 + lane]);
        float2 a = __half22float2(*reinterpret_cast<__half2*>(&u.x));
        float2 b = __half22float2(*reinterpret_cast<__half2*>(&u.y));
        acc = make_float4(a.x, a.y, b.x, b.y);
    }
    int j = g_rowptr[gw], e = g_rowptr[gw + 1];

    int i0, i1, i2, i3, i4, i5, i6, i7;
    bool have = (j + 8 <= e);
    if (have) {
        i0 = __ldg(&es[j]);     i1 = __ldg(&es[j + 1]);
        i2 = __ldg(&es[j + 2]); i3 = __ldg(&es[j + 3]);
        i4 = __ldg(&es[j + 4]); i5 = __ldg(&es[j + 5]);
        i6 = __ldg(&es[j + 6]); i7 = __ldg(&es[j + 7]);
    }
    #pragma unroll 1
    while (have) {
        uint2 uu[8];
        uu[0] = __ldg(&h2[i0 * 32 + lane]);
        uu[1] = __ldg(&h2[i1 * 32 + lane]);
        uu[2] = __ldg(&h2[i2 * 32 + lane]);
        uu[3] = __ldg(&h2[i3 * 32 + lane]);
        uu[4] = __ldg(&h2[i4 * 32 + lane]);
        uu[5] = __ldg(&h2[i5 * 32 + lane]);
        uu[6] = __ldg(&h2[i6 * 32 + lane]);
        uu[7] = __ldg(&h2[i7 * 32 + lane]);
        bool nxt = (j + 16 <= e);
        int x0, x1, x2, x3, x4, x5, x6, x7;
        if (nxt) {
            x0 = __ldg(&es[j + 8]);  x1 = __ldg(&es[j + 9]);
            x2 = __ldg(&es[j + 10]); x3 = __ldg(&es[j + 11]);
            x4 = __ldg(&es[j + 12]); x5 = __ldg(&es[j + 13]);
            x6 = __ldg(&es[j + 14]); x7 = __ldg(&es[j + 15]);
        }
        #pragma unroll
        for (int q = 0; q < 8; q++) {
            float2 a = __half22float2(*reinterpret_cast<__half2*>(&uu[q].x));
            float2 b = __half22float2(*reinterpret_cast<__half2*>(&uu[q].y));
            acc.x += a.x; acc.y += a.y; acc.z += b.x; acc.w += b.y;
        }
        j += 8;
        if (nxt) { i0 = x0; i1 = x1; i2 = x2; i3 = x3;
                   i4 = x4; i5 = x5; i6 = x6; i7 = x7; }
        have = nxt;
    }
    for (; j < e; j++) {
        int s = __ldg(&es[j]);
        uint2 u = __ldg(&h2[s * 32 + lane]);
        float2 a = __half22float2(*reinterpret_cast<__half2*>(&u.x));
        float2 b = __half22float2(*reinterpret_cast<__half2*>(&u.y));
        acc.x += a.x; acc.y += a.y; acc.z += b.x; acc.w += b.y;
    }

    // bf16 hi/lo split, write swizzled into tile planes
    __nv_bfloat16 h0 = __float2bfloat16(acc.x);
    __nv_bfloat16 h1 = __float2bfloat16(acc.y);
    __nv_bfloat16 h2v = __float2bfloat16(acc.z);
    __nv_bfloat16 h3 = __float2bfloat16(acc.w);
    __nv_bfloat16 l0 = __float2bfloat16(acc.x - __bfloat162float(h0));
    __nv_bfloat16 l1 = __float2bfloat16(acc.y - __bfloat162float(h1));
    __nv_bfloat16 l2 = __float2bfloat16(acc.z - __bfloat162float(h2v));
    __nv_bfloat16 l3 = __float2bfloat16(acc.w - __bfloat162float(h3));

    int tile = gw >> 6, row = gw & 63;
    int col = lane * 4;
    uint32_t off = (uint32_t)(tile * 16384 + row * 256
                              + (((col >> 3) ^ (row & 7)) << 4) + (col & 7) * 2);
    __nv_bfloat162 ph0 = __halves2bfloat162(h0, h1);
    __nv_bfloat162 ph1 = __halves2bfloat162(h2v, h3);
    __nv_bfloat162 pl0 = __halves2bfloat162(l0, l1);
    __nv_bfloat162 pl1 = __halves2bfloat162(l2, l3);
    uint2 hw, lw;
    hw.x = reinterpret_cast<uint32_t&>(ph0);
    hw.y = reinterpret_cast<uint32_t&>(ph1);
    lw.x = reinterpret_cast<uint32_t&>(pl0);
    lw.y = reinterpret_cast<uint32_t&>(pl1);
    *reinterpret_cast<uint2*>(reinterpret_cast<char*>(g_ahi) + off) = hw;
    *reinterpret_cast<uint2*>(reinterpret_cast<char*>(g_alo) + off) = lw;
}

// ---------------- warp-MMA helpers ------------------------------------------
__device__ __forceinline__ uint32_t smem_u32(const void* p) {
    uint32_t a;
    asm("{ .reg .u64 t; cvta.to.shared.u64 t, %1; cvt.u32.u64 %0, t; }"
        : "=r"(a) : "l"(p));
    return a;
}
__device__ __forceinline__ void ldsm4(unsigned r[4], uint32_t addr) {
    asm volatile("ldmatrix.sync.aligned.m8n8.x4.shared.b16 {%0,%1,%2,%3}, [%4];"
                 : "=r"(r[0]), "=r"(r[1]), "=r"(r[2]), "=r"(r[3]) : "r"(addr));
}
__device__ __forceinline__ void mma16816(float c[4], const unsigned a[4],
                                         const unsigned b[2]) {
    asm volatile(
        "mma.sync.aligned.m16n8k16.row.col.f32.bf16.bf16.f32 "
        "{%0,%1,%2,%3}, {%4,%5,%6,%7}, {%8,%9}, {%0,%1,%2,%3};"
        : "+f"(c[0]), "+f"(c[1]), "+f"(c[2]), "+f"(c[3])
        : "r"(a[0]), "r"(a[1]), "r"(a[2]), "r"(a[3]), "r"(b[0]), "r"(b[1]));
}

// 64x128 @ 128x128 stage; warp = 32 rows x 32 cols (2 m-tiles x 4 n-tiles)
__device__ __forceinline__ void mma_stage(uint32_t aHi, uint32_t aLo,
                                          uint32_t wHi, uint32_t wLo,
                                          int mhalf, int nq, int lane,
                                          float c[2][4][4]) {
    #pragma unroll
    for (int mt = 0; mt < 2; mt++)
        #pragma unroll
        for (int nt = 0; nt < 4; nt++)
            #pragma unroll
            for (int q = 0; q < 4; q++) c[mt][nt][q] = 0.f;

    int m = lane >> 3, r = lane & 7;
    uint32_t aRow[2], bRow[2];
    #pragma unroll
    for (int mt = 0; mt < 2; mt++)
        aRow[mt] = (uint32_t)(mhalf * 32 + mt * 16 + (m & 1) * 8 + r) * 256;
    #pragma unroll
    for (int bt = 0; bt < 2; bt++)
        bRow[bt] = (uint32_t)(nq * 32 + bt * 16 + (m >> 1) * 8 + r) * 256;
    int aAdd = m >> 1, bAdd = m & 1;

    #pragma unroll
    for (int k = 0; k < 8; k++) {
        unsigned ah[2][4], al[2][4], bh[2][4], bl[2][4];
        uint32_t ac = (uint32_t)(((k * 2 + aAdd) ^ r) << 4);
        uint32_t bc = (uint32_t)(((k * 2 + bAdd) ^ r) << 4);
        #pragma unroll
        for (int mt = 0; mt < 2; mt++) {
            ldsm4(ah[mt], aHi + aRow[mt] + ac);
            ldsm4(al[mt], aLo + aRow[mt] + ac);
        }
        #pragma unroll
        for (int bt = 0; bt < 2; bt++) {
            ldsm4(bh[bt], wHi + bRow[bt] + bc);
            ldsm4(bl[bt], wLo + bRow[bt] + bc);
        }
        #pragma unroll
        for (int mt = 0; mt < 2; mt++)
            #pragma unroll
            for (int nt = 0; nt < 4; nt++) {
                const unsigned* BH = bh[nt >> 1] + (nt & 1) * 2;
                const unsigned* BL = bl[nt >> 1] + (nt & 1) * 2;
                mma16816(c[mt][nt], ah[mt], BH);
                mma16816(c[mt][nt], al[mt], BH);
                mma16816(c[mt][nt], ah[mt], BL);
            }
    }
}

__device__ __forceinline__ void store_hilo(char* pH, char* pL, int row, int col,
                                           float f0, float f1) {
    __nv_bfloat16 h0 = __float2bfloat16(f0), h1 = __float2bfloat16(f1);
    __nv_bfloat16 l0 = __float2bfloat16(f0 - __bfloat162float(h0));
    __nv_bfloat16 l1 = __float2bfloat16(f1 - __bfloat162float(h1));
    uint32_t off = (uint32_t)(row * 256 + (((col >> 3) ^ (row & 7)) << 4)
                              + (col & 7) * 2);
    *(__nv_bfloat162*)(pH + off) = __halves2bfloat162(h0, h1);
    *(__nv_bfloat162*)(pL + off) = __halves2bfloat162(l0, l1);
}

__device__ __forceinline__ void stcs2(float* p, float v0, float v1) {
    asm volatile("st.global.cs.v2.f32 [%0], {%1,%2};" :: "l"(p), "f"(v0), "f"(v1)
                 : "memory");
}
__device__ __forceinline__ void stcsh2(__half* p, float v0, float v1) {
    __half2 h = __floats2half2_rn(v0, v1);
    unsigned u = reinterpret_cast<unsigned&>(h);
    asm volatile("st.global.cs.u32 [%0], %1;" :: "l"(p), "r"(u) : "memory");
}

// ---------------- MMA kernel: plane copy -> MMA1 -> relu -> MMA2 ------------
__global__ void __launch_bounds__(256, 2) mma_kernel(
        const float* __restrict__ b1, const float* __restrict__ b2,
        float* __restrict__ hout32, __half* __restrict__ hout16,
        int widx, int relu2) {
    extern __shared__ char smem[];
    char* pAhi = smem;             // 64 x 256B = 16KB
    char* pAlo = smem + 16384;
    char* pWhi = smem + 32768;     // 128 x 256B = 32KB
    char* pWlo = smem + 65536;

    int tid = threadIdx.x;
    int lane = tid & 31, wid = tid >> 5;
    int nodeBase = blockIdx.x * 64;

    // ---- stage W1 + A planes (linear copies; layouts pre-swizzled) ----
    {
        const float4* sh = (const float4*)g_whi[widx];
        const float4* sl = (const float4*)g_wlo[widx];
        const float4* aH = (const float4*)(g_ahi + (size_t)blockIdx.x * 8192);
        const float4* aL = (const float4*)(g_alo + (size_t)blockIdx.x * 8192);
        float4* dWh = (float4*)pWhi;
        float4* dWl = (float4*)pWlo;
        float4* dAh = (float4*)pAhi;
        float4* dAl = (float4*)pAlo;
        #pragma unroll
        for (int i = 0; i < 4; i++) {
            int j = tid + 256 * i;
            dAh[j] = aH[j];
            dAl[j] = aL[j];
        }
        #pragma unroll
        for (int i = 0; i < 8; i++) {
            int j = tid + 256 * i;
            dWh[j] = sh[j];
            dWl[j] = sl[j];
        }
    }
    __syncthreads();

    uint32_t aHi = smem_u32(pAhi), aLo = smem_u32(pAlo);
    uint32_t wHi = smem_u32(pWhi), wLo = smem_u32(pWlo);
    int mhalf = wid & 1;
    int nq = wid >> 1;
    int gid = lane >> 2, lc = (lane & 3) * 2;

    float c[2][4][4];
    mma_stage(aHi, aLo, wHi, wLo, mhalf, nq, lane, c);
    __syncthreads();

    // ---- epilogue 1: relu(C+b1) -> bf16 hi/lo into A tiles ----
    #pragma unroll
    for (int mt = 0; mt < 2; mt++)
        #pragma unroll
        for (int nt = 0; nt < 4; nt++) {
            int col = nq * 32 + nt * 8 + lc;
            float2 bb = *(const float2*)&b1[col];
            int r0 = mhalf * 32 + mt * 16 + gid;
            float f0 = fmaxf(c[mt][nt][0] + bb.x, 0.f);
            float f1 = fmaxf(c[mt][nt][1] + bb.y, 0.f);
            float f2 = fmaxf(c[mt][nt][2] + bb.x, 0.f);
            float f3 = fmaxf(c[mt][nt][3] + bb.y, 0.f);
            store_hilo(pAhi, pAlo, r0,     col, f0, f1);
            store_hilo(pAhi, pAlo, r0 + 8, col, f2, f3);
        }

    // ---- stage W2 ----
    {
        const float4* sh = (const float4*)g_whi[widx + 1];
        const float4* sl = (const float4*)g_wlo[widx + 1];
        float4* dh = (float4*)pWhi;
        float4* dl = (float4*)pWlo;
        #pragma unroll
        for (int i = 0; i < 8; i++) {
            int j = tid + 256 * i;
            dh[j] = sh[j];
            dl[j] = sl[j];
        }
    }
    __syncthreads();

    mma_stage(aHi, aLo, wHi, wLo, mhalf, nq, lane, c);

    // ---- epilogue 2: C + b2 (+relu) -> gmem ----
    #pragma unroll
    for (int mt = 0; mt < 2; mt++)
        #pragma unroll
        for (int nt = 0; nt < 4; nt++) {
            int col = nq * 32 + nt * 8 + lc;
            float2 bb = *(const float2*)&b2[col];
            float v0 = c[mt][nt][0] + bb.x;
            float v1 = c[mt][nt][1] + bb.y;
            float v2 = c[mt][nt][2] + bb.x;
            float v3 = c[mt][nt][3] + bb.y;
            if (relu2) {
                v0 = fmaxf(v0, 0.f); v1 = fmaxf(v1, 0.f);
                v2 = fmaxf(v2, 0.f); v3 = fmaxf(v3, 0.f);
            }
            int r0 = mhalf * 32 + mt * 16 + gid;
            int n0 = nodeBase + r0;
            int n1 = n0 + 8;
            if (relu2) {   // intermediate layers: fp16 activations
                if (n0 < NN) stcsh2(&hout16[n0 * DD + col], v0, v1);
                if (n1 < NN) stcsh2(&hout16[n1 * DD + col], v2, v3);
            } else {       // last layer: fp32 for pooling
                if (n0 < NN) stcs2(&hout32[n0 * DD + col], v0, v1);
                if (n1 < NN) stcs2(&hout32[n1 * DD + col], v2, v3);
            }
        }
}

// ---------------- mean pool over sorted batch + cleanup ----------------------
__device__ __forceinline__ int lbound_batch(const void* b, int val, int is64) {
    int lo = 0, hi = NN;
    if (is64) {
        const long long* p = (const long long*)b;
        long long v = val;
        while (lo < hi) { int mid = (lo + hi) >> 1; if (p[mid] < v) lo = mid + 1; else hi = mid; }
    } else {
        const int* p = (const int*)b;
        while (lo < hi) { int mid = (lo + hi) >> 1; if (p[mid] < val) lo = mid + 1; else hi = mid; }
    }
    return lo;
}

__global__ void pool_kernel(const float* __restrict__ h,
                            const void* __restrict__ batch,
                            const void* __restrict__ ei,
                            float* __restrict__ out) {
    // fused cleanup: restore invariants for the next kernel_launch call
    {
        int gtid = blockIdx.x * 512 + threadIdx.x;   // 65536 threads
        g_deg[gtid] = 0;
        int g2 = gtid + 65536;
        if (g2 < NN) g_deg[g2] = 0;
        if (gtid < NB) g_desc[gtid] = 0ULL;
    }
    __shared__ int s_is64;
    if (threadIdx.x == 0) s_is64 = detect64(ei);
    __syncthreads();
    int g = blockIdx.x;
    int d = threadIdx.x & 127;
    int sub = threadIdx.x >> 7;
    int start = lbound_batch(batch, g, s_is64);
    int end   = lbound_batch(batch, g + 1, s_is64);
    float acc = 0.f;
    for (int n = start + sub; n < end; n += 4)
        acc += h[n * DD + d];
    __shared__ float red[512];
    red[threadIdx.x] = acc;
    __syncthreads();
    if (sub == 0) {
        float s = (red[d] + red[d + 128]) + (red[d + 256] + red[d + 384]);
        int cnt = end - start;
        out[g * DD + d] = s / (float)(cnt > 0 ? cnt : 1);
    }
}

// ---------------- launch ------------------------------------------------------
extern "C" void kernel_launch(void* const* d_in, const int* in_sizes, int n_in,
                              void* d_out, int out_size) {
    const float* x = (const float*)d_in[0];
    const void* ei = d_in[1];
    const void* batch = d_in[2];
    const float *W1[3], *b1[3], *W2[3], *b2[3];
    for (int l = 0; l < 3; l++) {
        W1[l] = (const float*)d_in[3 + 4 * l];
        b1[l] = (const float*)d_in[4 + 4 * l];
        W2[l] = (const float*)d_in[5 + 4 * l];
        b2[l] = (const float*)d_in[6 + 4 * l];
    }
    float* out = (float*)d_out;

    cudaFuncSetAttribute(mma_kernel,
                         cudaFuncAttributeMaxDynamicSharedMemorySize, 98304);

    float* h;
    __half *xh, *hh0, *hh1;
    cudaGetSymbolAddress((void**)&h, g_h);
    cudaGetSymbolAddress((void**)&xh, g_xh);
    cudaGetSymbolAddress((void**)&hh0, g_hh0);
    cudaGetSymbolAddress((void**)&hh1, g_hh1);

    const int agg_blocks = (NN * 32 + 255) / 256;   // 12500

    pre_kernel<<<6 + HISTB + XCONVB, 512>>>(ei, x, W1[0], W2[0], W1[1], W2[1],
                                            W1[2], W2[2]);                       // 0
    scan_kernel<<<NB, 512>>>();                                                   // 1
    fill_kernel<<<NE / 512, 512>>>(ei);                                           // 2

    agg_kernel<<<agg_blocks, 256>>>(xh);                                          // 3 (profiled)
    mma_kernel<<<TLCNT, 256, 98304>>>(b1[0], b2[0], nullptr, hh0, 0, 1);          // 4
    agg_kernel<<<agg_blocks, 256>>>(hh0);                                         // 5
    mma_kernel<<<TLCNT, 256, 98304>>>(b1[1], b2[1], nullptr, hh1, 2, 1);          // 6
    agg_kernel<<<agg_blocks, 256>>>(hh1);                                         // 7
    mma_kernel<<<TLCNT, 256, 98304>>>(b1[2], b2[2], h, nullptr, 4, 0);            // 8

    pool_kernel<<<NG, 512>>>(h, batch, ei, out);                                  // 9
}

// round 10
// speedup vs baseline: 3.0254x; 1.1657x over previous
#include <cuda_runtime.h>
#include <cuda_bf16.h>
#include <cuda_fp16.h>
#include <cstdint>

#define NN 100000
#define NE 1600000
#define DD 128
#define NG 128
#define NB 196              // scan blocks: 196*512 >= NN
#define TLCNT 1563          // (NN+63)/64 tiles of 64 rows
#define HISTB 3125          // NE/512
#define XCONVB 3125         // NN*DD/4096

// ---------------- scratch (static device globals; zero-initialized) ---------
__device__ __align__(16) float g_h[NN * DD];        // final fp32 activations
__device__ __align__(16) __half g_xh[NN * DD];      // fp16 copy of input x
__device__ __align__(16) __half g_hh0[NN * DD];     // fp16 activations (layer0 out)
__device__ __align__(16) __half g_hh1[NN * DD];     // fp16 activations (layer1 out)
__device__ int g_deg[NN];
__device__ int g_rowptr[NN + 1];
__device__ int g_cursor[NN];
__device__ int g_esorted[NE];
__device__ unsigned long long g_desc[NB];
// aggregated tiles: single fp16 plane, pre-swizzled in MMA smem layout
__device__ __align__(16) __half g_a16[TLCNT * 8192];
// pre-transposed, pre-swizzled fp16 hi/lo weights {W1_0,W2_0,W1_1,W2_1,W1_2,W2_2}
__device__ __align__(16) __half g_whi[6][16384];
__device__ __align__(16) __half g_wlo[6][16384];

__device__ __forceinline__ __half2 U2H(unsigned u) {
    return *reinterpret_cast<__half2*>(&u);
}

// ---------------- inline index-width detection ------------------------------
__device__ __forceinline__ int detect64(const void* p) {
    const unsigned* w = (const unsigned*)p;
    unsigned acc = 0;
    #pragma unroll
    for (int i = 0; i < 16; i++) acc |= w[2 * i + 1];
    return acc == 0u;
}

// ---------------- launch 0: weight prep + degree hist + x->fp16 -------------
__device__ __forceinline__ uint32_t w_off(int n, int k) {
    return (uint32_t)(n * 128 + (((k >> 3) ^ (n & 7)) << 3) + (k & 7));
}

__global__ void __launch_bounds__(512) pre_kernel(
        const void* __restrict__ ei, const float* __restrict__ x,
        const float* w0, const float* w1, const float* w2,
        const float* w3, const float* w4, const float* w5) {
    if (blockIdx.x < 6) {
        const float* src[6] = {w0, w1, w2, w3, w4, w5};
        const float* W = src[blockIdx.x];
        for (int i = threadIdx.x; i < 16384; i += 512) {
            int k = i >> 7, n = i & 127;
            float v = W[i];
            __half hi = __float2half_rn(v);
            __half lo = __float2half_rn(v - __half2float(hi));
            uint32_t idx = w_off(n, k);
            g_whi[blockIdx.x][idx] = hi;
            g_wlo[blockIdx.x][idx] = lo;
        }
        return;
    }
    if (blockIdx.x >= 6 + HISTB) {
        // x -> fp16 conversion: thread handles 8 consecutive floats
        int base = (blockIdx.x - 6 - HISTB) * 4096 + threadIdx.x * 8;
        float4 a = __ldg((const float4*)(x + base));
        float4 b = __ldg((const float4*)(x + base + 4));
        __half2 p0 = __floats2half2_rn(a.x, a.y);
        __half2 p1 = __floats2half2_rn(a.z, a.w);
        __half2 p2 = __floats2half2_rn(b.x, b.y);
        __half2 p3 = __floats2half2_rn(b.z, b.w);
        uint4 u;
        u.x = reinterpret_cast<uint32_t&>(p0);
        u.y = reinterpret_cast<uint32_t&>(p1);
        u.z = reinterpret_cast<uint32_t&>(p2);
        u.w = reinterpret_cast<uint32_t&>(p3);
        *reinterpret_cast<uint4*>(g_xh + base) = u;
        return;
    }
    __shared__ int s_is64;
    if (threadIdx.x == 0) s_is64 = detect64(ei);
    __syncthreads();
    int e = (blockIdx.x - 6) * 512 + threadIdx.x;   // grid exact
    int dst = s_is64 ? (int)((const long long*)ei)[(long)NE + e]
                     : ((const int*)ei)[NE + e];
    atomicAdd(&g_deg[dst], 1);
}

// ---------------- launch 1: single-kernel exclusive scan ---------------------
__global__ void __launch_bounds__(512) scan_kernel() {
    int b = blockIdx.x, t = threadIdx.x;
    int idx = b * 512 + t;
    int v = (idx < NN) ? g_deg[idx] : 0;
    int lane = t & 31, w = t >> 5;
    int x = v;
    #pragma unroll
    for (int o = 1; o < 32; o <<= 1) {
        int u = __shfl_up_sync(~0u, x, o);
        if (lane >= o) x += u;
    }
    __shared__ int ws[16], wo[16];
    __shared__ int s_prefix, s_total;
    if (lane == 31) ws[w] = x;
    __syncthreads();
    if (t < 16) {
        int y = ws[t], z = y;
        #pragma unroll
        for (int o = 1; o < 16; o <<= 1) {
            int u = __shfl_up_sync(0xffffu, z, o, 16);
            if (t >= o) z += u;
        }
        wo[t] = z - y;
        if (t == 15) s_total = z;
    }
    __syncthreads();
    int incl = x + wo[w];
    if (t == 0)
        atomicExch(&g_desc[b], (1ULL << 32) | (unsigned)s_total);   // AGGREGATE
    if (t < 32) {
        long long running = 0;
        int i = b - 1 - t;
        while (true) {
            unsigned long long d = (2ULL << 32);
            if (i >= 0) {
                do { d = atomicAdd(&g_desc[i], 0ULL); } while ((d >> 32) == 0ULL);
            }
            int isPre = ((d >> 32) == 2ULL);
            unsigned pm = __ballot_sync(~0u, isPre);
            if (pm) {
                int fp = __ffs(pm) - 1;
                long long val = (t <= fp) ? (long long)(unsigned)d : 0;
                #pragma unroll
                for (int o = 16; o; o >>= 1) val += __shfl_down_sync(~0u, val, o);
                running += __shfl_sync(~0u, val, 0);
                break;
            } else {
                long long val = (long long)(unsigned)d;
                #pragma unroll
                for (int o = 16; o; o >>= 1) val += __shfl_down_sync(~0u, val, o);
                running += __shfl_sync(~0u, val, 0);
                i -= 32;
            }
        }
        if (t == 0) {
            s_prefix = (int)running;
            atomicExch(&g_desc[b],
                       (2ULL << 32) | (unsigned)(running + s_total));   // PREFIX
        }
    }
    __syncthreads();
    int excl = s_prefix + incl - v;
    if (idx < NN) { g_rowptr[idx] = excl; g_cursor[idx] = excl; }
    if (idx == NN - 1) g_rowptr[NN] = s_prefix + incl;
}

// ---------------- launch 2: CSR fill ----------------------------------------
__global__ void __launch_bounds__(512) fill_kernel(const void* __restrict__ ei) {
    __shared__ int s_is64;
    if (threadIdx.x == 0) s_is64 = detect64(ei);
    __syncthreads();
    int e = blockIdx.x * 512 + threadIdx.x;   // grid exact
    int dst, src;
    if (s_is64) {
        dst = (int)((const long long*)ei)[(long)NE + e];
        src = (int)((const long long*)ei)[e];
    } else {
        dst = ((const int*)ei)[NE + e];
        src = ((const int*)ei)[e];
    }
    int pos = atomicAdd(&g_cursor[dst], 1);
    g_esorted[pos] = src;
}

// ---------------- aggregation: warp-per-node, fp16 tree accumulation --------
__global__ void __launch_bounds__(256) agg_kernel(const __half* __restrict__ hin) {
    int gw = (blockIdx.x * 256 + threadIdx.x) >> 5;   // node index
    if (gw >= NN) return;
    int lane = threadIdx.x & 31;
    const uint2* h2 = (const uint2*)hin;
    const int* es = g_esorted;

    float4 acc;
    {
        uint2 u = __ldg(&h2[gw * 32 + lane]);
        float2 a = __half22float2(U2H(u.x));
        float2 b = __half22float2(U2H(u.y));
        acc = make_float4(a.x, a.y, b.x, b.y);
    }
    int j = g_rowptr[gw], e = g_rowptr[gw + 1];

    int i0, i1, i2, i3, i4, i5, i6, i7;
    bool have = (j + 8 <= e);
    if (have) {
        i0 = __ldg(&es[j]);     i1 = __ldg(&es[j + 1]);
        i2 = __ldg(&es[j + 2]); i3 = __ldg(&es[j + 3]);
        i4 = __ldg(&es[j + 4]); i5 = __ldg(&es[j + 5]);
        i6 = __ldg(&es[j + 6]); i7 = __ldg(&es[j + 7]);
    }
    #pragma unroll 1
    while (have) {
        uint2 uu[8];
        uu[0] = __ldg(&h2[i0 * 32 + lane]);
        uu[1] = __ldg(&h2[i1 * 32 + lane]);
        uu[2] = __ldg(&h2[i2 * 32 + lane]);
        uu[3] = __ldg(&h2[i3 * 32 + lane]);
        uu[4] = __ldg(&h2[i4 * 32 + lane]);
        uu[5] = __ldg(&h2[i5 * 32 + lane]);
        uu[6] = __ldg(&h2[i6 * 32 + lane]);
        uu[7] = __ldg(&h2[i7 * 32 + lane]);
        bool nxt = (j + 16 <= e);
        int x0, x1, x2, x3, x4, x5, x6, x7;
        if (nxt) {
            x0 = __ldg(&es[j + 8]);  x1 = __ldg(&es[j + 9]);
            x2 = __ldg(&es[j + 10]); x3 = __ldg(&es[j + 11]);
            x4 = __ldg(&es[j + 12]); x5 = __ldg(&es[j + 13]);
            x6 = __ldg(&es[j + 14]); x7 = __ldg(&es[j + 15]);
        }
        // fp16 tree sum of 8 edges (error pooled away downstream)
        __half2 sx = __hadd2(__hadd2(__hadd2(U2H(uu[0].x), U2H(uu[1].x)),
                                     __hadd2(U2H(uu[2].x), U2H(uu[3].x))),
                             __hadd2(__hadd2(U2H(uu[4].x), U2H(uu[5].x)),
                                     __hadd2(U2H(uu[6].x), U2H(uu[7].x))));
        __half2 sy = __hadd2(__hadd2(__hadd2(U2H(uu[0].y), U2H(uu[1].y)),
                                     __hadd2(U2H(uu[2].y), U2H(uu[3].y))),
                             __hadd2(__hadd2(U2H(uu[4].y), U2H(uu[5].y)),
                                     __hadd2(U2H(uu[6].y), U2H(uu[7].y))));
        float2 f0 = __half22float2(sx);
        float2 f1 = __half22float2(sy);
        acc.x += f0.x; acc.y += f0.y; acc.z += f1.x; acc.w += f1.y;
        j += 8;
        if (nxt) { i0 = x0; i1 = x1; i2 = x2; i3 = x3;
                   i4 = x4; i5 = x5; i6 = x6; i7 = x7; }
        have = nxt;
    }
    for (; j < e; j++) {
        int s = __ldg(&es[j]);
        uint2 u = __ldg(&h2[s * 32 + lane]);
        float2 a = __half22float2(U2H(u.x));
        float2 b = __half22float2(U2H(u.y));
        acc.x += a.x; acc.y += a.y; acc.z += b.x; acc.w += b.y;
    }

    // single fp16 plane, swizzled MMA tile layout
    int tile = gw >> 6, row = gw & 63;
    int col = lane * 4;
    uint32_t off = (uint32_t)(tile * 16384 + row * 256
                              + (((col >> 3) ^ (row & 7)) << 4) + (col & 7) * 2);
    __half2 p0 = __floats2half2_rn(acc.x, acc.y);
    __half2 p1 = __floats2half2_rn(acc.z, acc.w);
    uint2 u;
    u.x = reinterpret_cast<uint32_t&>(p0);
    u.y = reinterpret_cast<uint32_t&>(p1);
    *reinterpret_cast<uint2*>(reinterpret_cast<char*>(g_a16) + off) = u;
}

// ---------------- warp-MMA helpers ------------------------------------------
__device__ __forceinline__ uint32_t smem_u32(const void* p) {
    uint32_t a;
    asm("{ .reg .u64 t; cvta.to.shared.u64 t, %1; cvt.u32.u64 %0, t; }"
        : "=r"(a) : "l"(p));
    return a;
}
__device__ __forceinline__ void ldsm4(unsigned r[4], uint32_t addr) {
    asm volatile("ldmatrix.sync.aligned.m8n8.x4.shared.b16 {%0,%1,%2,%3}, [%4];"
                 : "=r"(r[0]), "=r"(r[1]), "=r"(r[2]), "=r"(r[3]) : "r"(addr));
}
__device__ __forceinline__ void mma16816(float c[4], const unsigned a[4],
                                         const unsigned b[2]) {
    asm volatile(
        "mma.sync.aligned.m16n8k16.row.col.f32.f16.f16.f32 "
        "{%0,%1,%2,%3}, {%4,%5,%6,%7}, {%8,%9}, {%0,%1,%2,%3};"
        : "+f"(c[0]), "+f"(c[1]), "+f"(c[2]), "+f"(c[3])
        : "r"(a[0]), "r"(a[1]), "r"(a[2]), "r"(a[3]), "r"(b[0]), "r"(b[1]));
}

// 64x128 @ 128x128 stage; warp = 32 rows x 32 cols (2 m-tiles x 4 n-tiles)
// A single fp16 plane; W fp16 hi/lo (2 products)
__device__ __forceinline__ void mma_stage(uint32_t aP,
                                          uint32_t wHi, uint32_t wLo,
                                          int mhalf, int nq, int lane,
                                          float c[2][4][4]) {
    #pragma unroll
    for (int mt = 0; mt < 2; mt++)
        #pragma unroll
        for (int nt = 0; nt < 4; nt++)
            #pragma unroll
            for (int q = 0; q < 4; q++) c[mt][nt][q] = 0.f;

    int m = lane >> 3, r = lane & 7;
    uint32_t aRow[2], bRow[2];
    #pragma unroll
    for (int mt = 0; mt < 2; mt++)
        aRow[mt] = (uint32_t)(mhalf * 32 + mt * 16 + (m & 1) * 8 + r) * 256;
    #pragma unroll
    for (int bt = 0; bt < 2; bt++)
        bRow[bt] = (uint32_t)(nq * 32 + bt * 16 + (m >> 1) * 8 + r) * 256;
    int aAdd = m >> 1, bAdd = m & 1;

    #pragma unroll
    for (int k = 0; k < 8; k++) {
        unsigned a[2][4], bh[2][4], bl[2][4];
        uint32_t ac = (uint32_t)(((k * 2 + aAdd) ^ r) << 4);
        uint32_t bc = (uint32_t)(((k * 2 + bAdd) ^ r) << 4);
        #pragma unroll
        for (int mt = 0; mt < 2; mt++)
            ldsm4(a[mt], aP + aRow[mt] + ac);
        #pragma unroll
        for (int bt = 0; bt < 2; bt++) {
            ldsm4(bh[bt], wHi + bRow[bt] + bc);
            ldsm4(bl[bt], wLo + bRow[bt] + bc);
        }
        #pragma unroll
        for (int mt = 0; mt < 2; mt++)
            #pragma unroll
            for (int nt = 0; nt < 4; nt++) {
                const unsigned* BH = bh[nt >> 1] + (nt & 1) * 2;
                const unsigned* BL = bl[nt >> 1] + (nt & 1) * 2;
                mma16816(c[mt][nt], a[mt], BH);
                mma16816(c[mt][nt], a[mt], BL);
            }
    }
}

__device__ __forceinline__ void store_h16(char* pA, int row, int col,
                                          float f0, float f1) {
    __half2 h = __floats2half2_rn(f0, f1);
    uint32_t off = (uint32_t)(row * 256 + (((col >> 3) ^ (row & 7)) << 4)
                              + (col & 7) * 2);
    *(__half2*)(pA + off) = h;
}

__device__ __forceinline__ void stcs2(float* p, float v0, float v1) {
    asm volatile("st.global.cs.v2.f32 [%0], {%1,%2};" :: "l"(p), "f"(v0), "f"(v1)
                 : "memory");
}
__device__ __forceinline__ void stcsh2(__half* p, float v0, float v1) {
    __half2 h = __floats2half2_rn(v0, v1);
    unsigned u = reinterpret_cast<unsigned&>(h);
    asm volatile("st.global.cs.u32 [%0], %1;" :: "l"(p), "r"(u) : "memory");
}

// ---------------- MMA kernel: plane copy -> MMA1 -> relu -> MMA2 ------------
// 256 threads, 64-row tile, 80KB smem -> 2 CTAs/SM.
__global__ void __launch_bounds__(256, 2) mma_kernel(
        const float* __restrict__ b1, const float* __restrict__ b2,
        float* __restrict__ hout32, __half* __restrict__ hout16,
        int widx, int relu2) {
    extern __shared__ char smem[];
    char* pA   = smem;             // 64 x 256B = 16KB
    char* pWhi = smem + 16384;     // 128 x 256B = 32KB
    char* pWlo = smem + 49152;     // 32KB

    int tid = threadIdx.x;
    int lane = tid & 31, wid = tid >> 5;
    int nodeBase = blockIdx.x * 64;

    // ---- stage W1 + A plane (linear copies; layouts pre-swizzled) ----
    {
        const float4* sh = (const float4*)g_whi[widx];
        const float4* sl = (const float4*)g_wlo[widx];
        const float4* aP = (const float4*)(g_a16 + (size_t)blockIdx.x * 8192);
        float4* dWh = (float4*)pWhi;
        float4* dWl = (float4*)pWlo;
        float4* dA  = (float4*)pA;
        #pragma unroll
        for (int i = 0; i < 4; i++) {
            int j = tid + 256 * i;
            dA[j] = aP[j];
        }
        #pragma unroll
        for (int i = 0; i < 8; i++) {
            int j = tid + 256 * i;
            dWh[j] = sh[j];
            dWl[j] = sl[j];
        }
    }
    __syncthreads();

    uint32_t aP = smem_u32(pA);
    uint32_t wHi = smem_u32(pWhi), wLo = smem_u32(pWlo);
    int mhalf = wid & 1;
    int nq = wid >> 1;
    int gid = lane >> 2, lc = (lane & 3) * 2;

    float c[2][4][4];
    mma_stage(aP, wHi, wLo, mhalf, nq, lane, c);
    __syncthreads();

    // ---- epilogue 1: relu(C+b1) -> fp16 into A plane ----
    #pragma unroll
    for (int mt = 0; mt < 2; mt++)
        #pragma unroll
        for (int nt = 0; nt < 4; nt++) {
            int col = nq * 32 + nt * 8 + lc;
            float2 bb = *(const float2*)&b1[col];
            int r0 = mhalf * 32 + mt * 16 + gid;
            float f0 = fmaxf(c[mt][nt][0] + bb.x, 0.f);
            float f1 = fmaxf(c[mt][nt][1] + bb.y, 0.f);
            float f2 = fmaxf(c[mt][nt][2] + bb.x, 0.f);
            float f3 = fmaxf(c[mt][nt][3] + bb.y, 0.f);
            store_h16(pA, r0,     col, f0, f1);
            store_h16(pA, r0 + 8, col, f2, f3);
        }

    // ---- stage W2 ----
    {
        const float4* sh = (const float4*)g_whi[widx + 1];
        const float4* sl = (const float4*)g_wlo[widx + 1];
        float4* dh = (float4*)pWhi;
        float4* dl = (float4*)pWlo;
        #pragma unroll
        for (int i = 0; i < 8; i++) {
            int j = tid + 256 * i;
            dh[j] = sh[j];
            dl[j] = sl[j];
        }
    }
    __syncthreads();

    mma_stage(aP, wHi, wLo, mhalf, nq, lane, c);

    // ---- epilogue 2: C + b2 (+relu) -> gmem ----
    #pragma unroll
    for (int mt = 0; mt < 2; mt++)
        #pragma unroll
        for (int nt = 0; nt < 4; nt++) {
            int col = nq * 32 + nt * 8 + lc;
            float2 bb = *(const float2*)&b2[col];
            float v0 = c[mt][nt][0] + bb.x;
            float v1 = c[mt][nt][1] + bb.y;
            float v2 = c[mt][nt][2] + bb.x;
            float v3 = c[mt][nt][3] + bb.y;
            if (relu2) {
                v0 = fmaxf(v0, 0.f); v1 = fmaxf(v1, 0.f);
                v2 = fmaxf(v2, 0.f); v3 = fmaxf(v3, 0.f);
            }
            int r0 = mhalf * 32 + mt * 16 + gid;
            int n0 = nodeBase + r0;
            int n1 = n0 + 8;
            if (relu2) {   // intermediate layers: fp16 activations
                if (n0 < NN) stcsh2(&hout16[n0 * DD + col], v0, v1);
                if (n1 < NN) stcsh2(&hout16[n1 * DD + col], v2, v3);
            } else {       // last layer: fp32 for pooling
                if (n0 < NN) stcs2(&hout32[n0 * DD + col], v0, v1);
                if (n1 < NN) stcs2(&hout32[n1 * DD + col], v2, v3);
            }
        }
}

// ---------------- mean pool over sorted batch + cleanup ----------------------
__device__ __forceinline__ int lbound_batch(const void* b, int val, int is64) {
    int lo = 0, hi = NN;
    if (is64) {
        const long long* p = (const long long*)b;
        long long v = val;
        while (lo < hi) { int mid = (lo + hi) >> 1; if (p[mid] < v) lo = mid + 1; else hi = mid; }
    } else {
        const int* p = (const int*)b;
        while (lo < hi) { int mid = (lo + hi) >> 1; if (p[mid] < val) lo = mid + 1; else hi = mid; }
    }
    return lo;
}

__global__ void pool_kernel(const float* __restrict__ h,
                            const void* __restrict__ batch,
                            const void* __restrict__ ei,
                            float* __restrict__ out) {
    // fused cleanup: restore invariants for the next kernel_launch call
    {
        int gtid = blockIdx.x * 512 + threadIdx.x;   // 65536 threads
        g_deg[gtid] = 0;
        int g2 = gtid + 65536;
        if (g2 < NN) g_deg[g2] = 0;
        if (gtid < NB) g_desc[gtid] = 0ULL;
    }
    __shared__ int s_is64;
    if (threadIdx.x == 0) s_is64 = detect64(ei);
    __syncthreads();
    int g = blockIdx.x;
    int d = threadIdx.x & 127;
    int sub = threadIdx.x >> 7;
    int start = lbound_batch(batch, g, s_is64);
    int end   = lbound_batch(batch, g + 1, s_is64);
    float acc = 0.f;
    for (int n = start + sub; n < end; n += 4)
        acc += h[n * DD + d];
    __shared__ float red[512];
    red[threadIdx.x] = acc;
    __syncthreads();
    if (sub == 0) {
        float s = (red[d] + red[d + 128]) + (red[d + 256] + red[d + 384]);
        int cnt = end - start;
        out[g * DD + d] = s / (float)(cnt > 0 ? cnt : 1);
    }
}

// ---------------- launch ------------------------------------------------------
extern "C" void kernel_launch(void* const* d_in, const int* in_sizes, int n_in,
                              void* d_out, int out_size) {
    const float* x = (const float*)d_in[0];
    const void* ei = d_in[1];
    const void* batch = d_in[2];
    const float *W1[3], *b1[3], *W2[3], *b2[3];
    for (int l = 0; l < 3; l++) {
        W1[l] = (const float*)d_in[3 + 4 * l];
        b1[l] = (const float*)d_in[4 + 4 * l];
        W2[l] = (const float*)d_in[5 + 4 * l];
        b2[l] = (const float*)d_in[6 + 4 * l];
    }
    float* out = (float*)d_out;

    cudaFuncSetAttribute(mma_kernel,
                         cudaFuncAttributeMaxDynamicSharedMemorySize, 81920);

    float* h;
    __half *xh, *hh0, *hh1;
    cudaGetSymbolAddress((void**)&h, g_h);
    cudaGetSymbolAddress((void**)&xh, g_xh);
    cudaGetSymbolAddress((void**)&hh0, g_hh0);
    cudaGetSymbolAddress((void**)&hh1, g_hh1);

    const int agg_blocks = (NN * 32 + 255) / 256;   // 12500

    pre_kernel<<<6 + HISTB + XCONVB, 512>>>(ei, x, W1[0], W2[0], W1[1], W2[1],
                                            W1[2], W2[2]);                       // 0
    scan_kernel<<<NB, 512>>>();                                                   // 1
    fill_kernel<<<NE / 512, 512>>>(ei);                                           // 2

    agg_kernel<<<agg_blocks, 256>>>(xh);                                          // 3 (profiled)
    mma_kernel<<<TLCNT, 256, 81920>>>(b1[0], b2[0], nullptr, hh0, 0, 1);          // 4
    agg_kernel<<<agg_blocks, 256>>>(hh0);                                         // 5
    mma_kernel<<<TLCNT, 256, 81920>>>(b1[1], b2[1], nullptr, hh1, 2, 1);          // 6
    agg_kernel<<<agg_blocks, 256>>>(hh1);                                         // 7
    mma_kernel<<<TLCNT, 256, 81920>>>(b1[2], b2[2], h, nullptr, 4, 0);            // 8

    pool_kernel<<<NG, 512>>>(h, batch, ei, out);                                  // 9
}